// round 3
// baseline (speedup 1.0000x reference)
#include <cuda_runtime.h>
#include <math.h>

typedef unsigned long long ull;

#define BB 16
#define TT 2048
#define DD 1280
#define BT (BB*TT)          // 32768
#define GCTA 128
#define ESL 10              // e-rows of W_h per CTA
#define REDS 168            // padded reduction stride (floats)

// -------- scratch (static __device__ — no runtime allocation) --------
__device__ float g_xproj[BT*DD];     // silu(x @ W_in^T[:, :D])   rows b*T+t
__device__ float g_sz[BT*DD];        // silu(x @ W_in^T[:, D:])   rows b*T+t
__device__ float g_xpre[BT*DD];      // x_proj @ W_x^T + b        rows t*B+b
__device__ float g_outpre[BT*DD];    // h_t * silu(z)             rows t*B+b
__device__ float g_h[2][BB*DD];      // double-buffered hidden state
__device__ ull   g_bar;              // global barrier arrival counter
__device__ ull   g_flag;             // global barrier release flag

// -------- packed f32x2 helpers --------
__device__ __forceinline__ ull ffma2(ull a, ull b, ull c){
    ull d; asm("fma.rn.f32x2 %0, %1, %2, %3;" : "=l"(d) : "l"(a), "l"(b), "l"(c)); return d;
}
__device__ __forceinline__ ull pk2(float x){
    ull d; asm("mov.b64 %0, {%1, %1};" : "=l"(d) : "f"(x)); return d;
}
__device__ __forceinline__ ull pkxy(float x, float y){
    ull d; asm("mov.b64 %0, {%1, %2};" : "=l"(d) : "f"(x), "f"(y)); return d;
}
__device__ __forceinline__ float2 unpk(ull v){
    float2 r; asm("mov.b64 {%0, %1}, %2;" : "=f"(r.x), "=f"(r.y) : "l"(v)); return r;
}
__device__ __forceinline__ float hadd(ull v){ float2 f = unpk(v); return f.x + f.y; }
__device__ __forceinline__ float silu_f(float v){ return v * (1.f/(1.f + __expf(-v))); }

// -------- prologue: zero h0, barrier counter, release flag --------
__global__ void reset_kernel(){
    int i = blockIdx.x*blockDim.x + threadIdx.x;
    if (i == 0){ g_bar = 0ULL; g_flag = 0ULL; }
    if (i < BB*DD) g_h[0][i] = 0.f;
}

// ============================================================================
// SGEMM: C = A(MxK) * Bw^T(NxK), K=1280. 128x128 tile, BK=16, 256 thr,
// 8x8/thread. A is stored in SMEM pre-duplicated as (a,a) u64 pairs so the
// inner loop has ZERO pack-MOVs: just LDS.128 + FFMA2.
// MODE 0: silu -> g_xproj (n<D) / g_sz (n>=D)
// MODE 1: +bias, permute rows (b*T+t)->(t*B+b) -> g_xpre
// MODE 2: permute rows (t*B+b)->(b,t) -> dout
// ============================================================================
template<int MODE>
__global__ __launch_bounds__(256,2)
void gemm_kernel(const float* __restrict__ A, const float* __restrict__ Bw,
                 const float* __restrict__ bias, float* __restrict__ dout){
    __shared__ ull   As2[16][132];   // duplicated A: As2[k][m] = (a,a)
    __shared__ float Bs [16][132];
    const int tid = threadIdx.x;
    const int m0 = blockIdx.x*128, n0 = blockIdx.y*128;
    const int tx = tid & 15, ty = tid >> 4;
    const int row0 = tid >> 2, row1 = row0 + 64;
    const int c4 = (tid & 3) << 2;

    const float* Ar0 = A  + (size_t)(m0+row0)*DD + c4;
    const float* Ar1 = A  + (size_t)(m0+row1)*DD + c4;
    const float* Br0 = Bw + (size_t)(n0+row0)*DD + c4;
    const float* Br1 = Bw + (size_t)(n0+row1)*DD + c4;

    float4 pa0 = *(const float4*)(Ar0);
    float4 pa1 = *(const float4*)(Ar1);
    float4 pb0 = *(const float4*)(Br0);
    float4 pb1 = *(const float4*)(Br1);

    ull acc[8][4];
    #pragma unroll
    for (int i=0;i<8;i++){
        #pragma unroll
        for (int j=0;j<4;j++) acc[i][j]=0ULL;
    }

    for (int kt=0; kt<DD; kt+=16){
        As2[c4+0][row0]=pk2(pa0.x); As2[c4+1][row0]=pk2(pa0.y);
        As2[c4+2][row0]=pk2(pa0.z); As2[c4+3][row0]=pk2(pa0.w);
        As2[c4+0][row1]=pk2(pa1.x); As2[c4+1][row1]=pk2(pa1.y);
        As2[c4+2][row1]=pk2(pa1.z); As2[c4+3][row1]=pk2(pa1.w);
        Bs[c4+0][row0]=pb0.x; Bs[c4+1][row0]=pb0.y; Bs[c4+2][row0]=pb0.z; Bs[c4+3][row0]=pb0.w;
        Bs[c4+0][row1]=pb1.x; Bs[c4+1][row1]=pb1.y; Bs[c4+2][row1]=pb1.z; Bs[c4+3][row1]=pb1.w;
        __syncthreads();

        if (kt + 16 < DD){
            pa0 = *(const float4*)(Ar0 + kt + 16);
            pa1 = *(const float4*)(Ar1 + kt + 16);
            pb0 = *(const float4*)(Br0 + kt + 16);
            pb1 = *(const float4*)(Br1 + kt + 16);
        }

        #pragma unroll
        for (int k=0;k<16;k++){
            ulonglong2 a0 = *(const ulonglong2*)&As2[k][ty*4];
            ulonglong2 a1 = *(const ulonglong2*)&As2[k][ty*4+2];
            ulonglong2 a2 = *(const ulonglong2*)&As2[k][64+ty*4];
            ulonglong2 a3 = *(const ulonglong2*)&As2[k][64+ty*4+2];
            ulonglong2 bl = *(const ulonglong2*)&Bs[k][tx*4];
            ulonglong2 bh = *(const ulonglong2*)&Bs[k][64+tx*4];
            ull av[8] = {a0.x,a0.y,a1.x,a1.y, a2.x,a2.y,a3.x,a3.y};
            #pragma unroll
            for (int i=0;i<8;i++){
                acc[i][0] = ffma2(av[i], bl.x, acc[i][0]);
                acc[i][1] = ffma2(av[i], bl.y, acc[i][1]);
                acc[i][2] = ffma2(av[i], bh.x, acc[i][2]);
                acc[i][3] = ffma2(av[i], bh.y, acc[i][3]);
            }
        }
        __syncthreads();
    }

    // epilogue
    #pragma unroll
    for (int i=0;i<8;i++){
        int m = m0 + ((i<4) ? (ty*4 + i) : (64 + ty*4 + i - 4));
        #pragma unroll
        for (int j=0;j<4;j++){
            int n = n0 + ((j<2) ? (tx*4 + j*2) : (64 + tx*4 + (j-2)*2));
            float2 v = unpk(acc[i][j]);
            if (MODE == 0){
                float2 s; s.x = silu_f(v.x); s.y = silu_f(v.y);
                if (n < DD) *(float2*)&g_xproj[(size_t)m*DD + n] = s;
                else        *(float2*)&g_sz   [(size_t)m*DD + (n-DD)] = s;
            } else if (MODE == 1){
                float2 s; s.x = v.x + bias[n]; s.y = v.y + bias[n+1];
                int ro = ((m & (TT-1)) << 4) | (m >> 11);   // (b*T+t) -> t*16+b
                *(float2*)&g_xpre[(size_t)ro*DD + n] = s;
            } else {
                int b = m & 15, t = m >> 4;                 // row = t*16+b
                *(float2*)&dout[(size_t)b*TT*DD + (size_t)t*DD + n] = v;
            }
        }
    }
}

// ============================================================================
// Persistent recurrence. 128 CTAs x 256 thr. W_h slice [10][1280] in SMEM,
// natural [e][k] layout (conflict-free, broadcast across b-groups).
// Each thread: 2 batch rows (b, b+8) x 10 e x 40 k-chunk -> each W LDS.128
// feeds 4 FFMA2. k split: 4 warp-quarters x 8 lane-chunks; reduce kq via
// warp bfly shuffles, quarters via tiny smem. Flag-release global barrier.
// ============================================================================
extern __shared__ float smem_dyn[];
__global__ __launch_bounds__(256,1)
void recur_kernel(const float* __restrict__ W_h, const float* __restrict__ xpre,
                  const float* __restrict__ sz, float* __restrict__ outpre,
                  float* __restrict__ dout_h){
    float* Wsh = smem_dyn;              // [10][1280]
    float* red = smem_dyn + ESL*DD;     // [4][REDS]
    const int tid = threadIdx.x;
    const int e0  = blockIdx.x * ESL;

    {   // W_h rows e0..e0+9 contiguous: straight float4 copy
        const float4* Wsrc = (const float4*)(W_h + (size_t)e0*DD);
        float4* Wdst = (float4*)Wsh;
        for (int idx = tid; idx < ESL*DD/4; idx += 256) Wdst[idx] = Wsrc[idx];
    }
    __syncthreads();

    const int w  = tid >> 5, l = tid & 31;
    const int kq = l & 7;                 // 8 chunks within quarter (contiguous 128B)
    const int bq = l >> 3;                // 4 b per warp
    const int q  = w >> 1;                // k-quarter (320 k each)
    const int b  = (w & 1)*4 + bq;        // b in 0..7; this thread also does b+8
    const int kbase = q*320 + kq*4;
    const int rb = tid / 10, re = tid - rb*10;      // epilogue map (tid<160)
    const bool epi = (tid < 160);

    for (int t=0; t<TT; t++){
        // prefetch epilogue operands
        float xp = 0.f, zz = 0.f;
        if (epi){
            xp = xpre[(size_t)(t*BB + rb)*DD + e0 + re];
            zz = sz[(size_t)rb*TT*DD + (size_t)t*DD + e0 + re];
        }

        const float* hb = g_h[t&1];
        const float* hp0 = hb + b*DD + kbase;
        const float* hp1 = hb + (b+8)*DD + kbase;
        ull acc0[10], acc1[10];
        #pragma unroll
        for (int e=0;e<10;e++){ acc0[e]=0ULL; acc1[e]=0ULL; }

        #pragma unroll 2
        for (int it=0; it<10; it++){
            float4 h0 = __ldcg((const float4*)(hp0 + it*32));
            float4 h1 = __ldcg((const float4*)(hp1 + it*32));
            ull p0a = pkxy(h0.x, h0.y), p0b = pkxy(h0.z, h0.w);
            ull p1a = pkxy(h1.x, h1.y), p1b = pkxy(h1.z, h1.w);
            const float* wp = Wsh + kbase + it*32;
            #pragma unroll
            for (int e=0;e<10;e++){
                ulonglong2 wv = *(const ulonglong2*)(wp + e*DD);
                acc0[e] = ffma2(p0a, wv.x, acc0[e]);
                acc0[e] = ffma2(p0b, wv.y, acc0[e]);
                acc1[e] = ffma2(p1a, wv.x, acc1[e]);
                acc1[e] = ffma2(p1b, wv.y, acc1[e]);
            }
        }

        float s0[10], s1[10];
        #pragma unroll
        for (int e=0;e<10;e++){ s0[e] = hadd(acc0[e]); s1[e] = hadd(acc1[e]); }
        #pragma unroll
        for (int d=1; d<8; d<<=1){
            #pragma unroll
            for (int e=0;e<10;e++){
                s0[e] += __shfl_xor_sync(0xffffffffu, s0[e], d);
                s1[e] += __shfl_xor_sync(0xffffffffu, s1[e], d);
            }
        }
        if (kq == 0){
            float* rp0 = red + q*REDS + b*10;
            float* rp1 = red + q*REDS + (b+8)*10;
            #pragma unroll
            for (int e=0;e<10;e+=2){
                *(float2*)(rp0+e) = make_float2(s0[e], s0[e+1]);
                *(float2*)(rp1+e) = make_float2(s1[e], s1[e+1]);
            }
        }
        __syncthreads();

        if (epi){
            float s = red[0*REDS+tid] + red[1*REDS+tid] + red[2*REDS+tid] + red[3*REDS+tid];
            float h = tanhf(xp + s);
            __stcg(&g_h[(t+1)&1][rb*DD + e0 + re], h);
            outpre[(size_t)(t*BB + rb)*DD + e0 + re] = h * zz;
            if (dout_h != nullptr && t == TT-1) dout_h[rb*DD + e0 + re] = h;
        }
        __threadfence();
        __syncthreads();
        if (tid == 0){
            ull old = atomicAdd(&g_bar, 1ULL);
            ull target = (ull)(t+1) * (ull)GCTA;
            if (old + 1ULL == target){
                __threadfence();
                atomicExch(&g_flag, target);
            } else {
                long long guard = 0;
                while (true){
                    ull f;
                    asm volatile("ld.global.cg.u64 %0, [%1];" : "=l"(f) : "l"(&g_flag));
                    if (f >= target) break;
                    if (++guard > 4000000LL) break;   // anti-hang bailout
                    __nanosleep(20);
                }
            }
            __threadfence();
        }
        __syncthreads();
    }
}

// ============================================================================
extern "C" void kernel_launch(void* const* d_in, const int* in_sizes, int n_in,
                              void* d_out, int out_size){
    const float* x     = (const float*)d_in[0];   // (16,2048,1280)
    const float* W_in  = (const float*)d_in[1];   // (2560,1280)
    const float* W_out = (const float*)d_in[2];   // (1280,1280)
    const float* W_x   = (const float*)d_in[3];   // (1280,1280)
    const float* W_h   = (const float*)d_in[4];   // (1280,1280)
    const float* bias  = (const float*)d_in[5];   // (1280,)
    float* out = (float*)d_out;

    const int recur_smem = (ESL*DD + 4*REDS) * 4;   // 53888 B
    cudaFuncSetAttribute(recur_kernel, cudaFuncAttributeMaxDynamicSharedMemorySize, recur_smem);

    float* dout_h = (out_size >= BT*DD + BB*DD) ? (out + (size_t)BT*DD) : nullptr;

    float* xproj_p; cudaGetSymbolAddress((void**)&xproj_p, g_xproj);
    float* xpre_p;  cudaGetSymbolAddress((void**)&xpre_p,  g_xpre);
    float* sz_p;    cudaGetSymbolAddress((void**)&sz_p,    g_sz);
    float* outpre_p;cudaGetSymbolAddress((void**)&outpre_p,g_outpre);

    reset_kernel<<<80, 256>>>();

    // GEMM1: xz = x @ W_in^T (fused silu on both halves)
    gemm_kernel<0><<<dim3(BT/128, (2*DD)/128), 256>>>(x, W_in, nullptr, nullptr);

    // GEMM2: x_pre = silu(xproj) @ W_x^T + b, stored (T,B,D)
    gemm_kernel<1><<<dim3(BT/128, DD/128), 256>>>(xproj_p, W_x, bias, nullptr);

    // Recurrence (persistent, 2048 steps)
    recur_kernel<<<GCTA, 256, recur_smem>>>(W_h, xpre_p, sz_p, outpre_p, dout_h);

    // GEMM3: out = out_pre @ W_out^T, permuted to (B,T,D) in d_out
    gemm_kernel<2><<<dim3(BT/128, DD/128), 256>>>(outpre_p, W_out, nullptr, out);
}

// round 5
// speedup vs baseline: 1.3331x; 1.3331x over previous
#include <cuda_runtime.h>
#include <cuda_bf16.h>
#include <math.h>
#include <stdint.h>

typedef unsigned long long ull;
typedef __nv_bfloat16 bf16;

#define BB 16
#define TT 2048
#define DD 1280
#define BT (BB*TT)          // 32768
#define GCTA 128
#define ESL 10
#define REDS 168
#define ASTR 40             // smem row stride (bf16) = 80B, conflict-free for ldmatrix

// ---------------- scratch (static __device__) ----------------
__device__ float g_sz[BT*DD];        // silu(z), fp32, rows b*T+t
__device__ float g_xpre[BT*DD];      // x_pre,   fp32, rows t*B+b
__device__ float g_h[2][BB*DD];
__device__ ull   g_bar;
__device__ ull   g_flag;

// bf16 hi/lo row-major operands
__device__ bf16 g_xt_hi[BT*DD],  g_xt_lo[BT*DD];     // x
__device__ bf16 g_pt_hi[BT*DD],  g_pt_lo[BT*DD];     // silu(xproj)
__device__ bf16 g_ot_hi[BT*DD],  g_ot_lo[BT*DD];     // h*silu(z), rows t*B+b
__device__ bf16 g_wi_hi[2*DD*DD], g_wi_lo[2*DD*DD];  // W_in
__device__ bf16 g_wx_hi[DD*DD],   g_wx_lo[DD*DD];    // W_x
__device__ bf16 g_wo_hi[DD*DD],   g_wo_lo[DD*DD];    // W_out

// ---------------- helpers ----------------
__device__ __forceinline__ ull ffma2(ull a, ull b, ull c){
    ull d; asm("fma.rn.f32x2 %0, %1, %2, %3;" : "=l"(d) : "l"(a), "l"(b), "l"(c)); return d;
}
__device__ __forceinline__ ull pkxy(float x, float y){
    ull d; asm("mov.b64 %0, {%1, %2};" : "=l"(d) : "f"(x), "f"(y)); return d;
}
__device__ __forceinline__ float2 unpk(ull v){
    float2 r; asm("mov.b64 {%0, %1}, %2;" : "=f"(r.x), "=f"(r.y) : "l"(v)); return r;
}
__device__ __forceinline__ float hadd(ull v){ float2 f = unpk(v); return f.x + f.y; }
__device__ __forceinline__ float silu_f(float v){ return v * (1.f/(1.f + __expf(-v))); }
__device__ __forceinline__ uint32_t smem_u32(const void* p){
    uint32_t a; asm("{ .reg .u64 t; cvta.to.shared.u64 t, %1; cvt.u32.u64 %0, t; }" : "=r"(a) : "l"(p));
    return a;
}
__device__ __forceinline__ void cpa16(uint32_t s, const void* g){
    asm volatile("cp.async.cg.shared.global [%0], [%1], 16;" :: "r"(s), "l"(g));
}
__device__ __forceinline__ void cpa_commit(){ asm volatile("cp.async.commit_group;"); }
__device__ __forceinline__ void cpa_wait1(){ asm volatile("cp.async.wait_group 1;"); }

__device__ __forceinline__ void ldsm4(uint32_t* r, uint32_t addr){
    asm volatile("ldmatrix.sync.aligned.m8n8.x4.shared.b16 {%0,%1,%2,%3}, [%4];"
        : "=r"(r[0]), "=r"(r[1]), "=r"(r[2]), "=r"(r[3]) : "r"(addr));
}
__device__ __forceinline__ void mma16816(float* c, const uint32_t* a, uint32_t b0, uint32_t b1){
    asm volatile("mma.sync.aligned.m16n8k16.row.col.f32.bf16.bf16.f32 "
        "{%0,%1,%2,%3}, {%4,%5,%6,%7}, {%8,%9}, {%0,%1,%2,%3};"
        : "+f"(c[0]), "+f"(c[1]), "+f"(c[2]), "+f"(c[3])
        : "r"(a[0]), "r"(a[1]), "r"(a[2]), "r"(a[3]), "r"(b0), "r"(b1));
}
__device__ __forceinline__ void hilo(float v, bf16& h, bf16& l){
    h = __float2bfloat16(v);
    l = __float2bfloat16(v - __bfloat162float(h));
}

// ---------------- reset ----------------
__global__ void reset_kernel(){
    int i = blockIdx.x*blockDim.x + threadIdx.x;
    if (i == 0){ g_bar = 0ULL; g_flag = 0ULL; }
    if (i < BB*DD) g_h[0][i] = 0.f;
}

// ---------------- fp32 -> bf16 hi/lo (row-major, elementwise) ----------------
__global__ void convert_hilo(const float* __restrict__ src, bf16* __restrict__ hi,
                             bf16* __restrict__ lo, int n4){
    int i = blockIdx.x*blockDim.x + threadIdx.x;
    if (i >= n4) return;
    float4 v = *(const float4*)(src + (size_t)i*4);
    bf16 h0,l0,h1,l1,h2,l2,h3,l3;
    hilo(v.x,h0,l0); hilo(v.y,h1,l1); hilo(v.z,h2,l2); hilo(v.w,h3,l3);
    __nv_bfloat162 hh0; hh0.x=h0; hh0.y=h1;
    __nv_bfloat162 hh1; hh1.x=h2; hh1.y=h3;
    __nv_bfloat162 ll0; ll0.x=l0; ll0.y=l1;
    __nv_bfloat162 ll1; ll1.x=l2; ll1.y=l3;
    *(__nv_bfloat162*)(hi + (size_t)i*4)     = hh0;
    *(__nv_bfloat162*)(hi + (size_t)i*4 + 2) = hh1;
    *(__nv_bfloat162*)(lo + (size_t)i*4)     = ll0;
    *(__nv_bfloat162*)(lo + (size_t)i*4 + 2) = ll1;
}

// ============================================================================
// bf16 mma.sync GEMM with 3-term hi/lo split. C = A(Mx1280) * Bw^T(Nx1280).
// 128x128 CTA tile, BK=32, 2-stage cp.async, 8 warps (2x4), 64x32 warp tiles.
// MODE 0: n<DD: silu -> pt hi/lo tiles; n>=DD: silu -> g_sz fp32
// MODE 1: +bias, rows (b*T+t)->(t*B+b), fp32 -> g_xpre
// MODE 2: rows (t*B+b)->(b,t,:), fp32 -> dout
// ============================================================================
template<int MODE>
__global__ __launch_bounds__(256,2)
void gemm_mma(const bf16* __restrict__ Ahi, const bf16* __restrict__ Alo,
              const bf16* __restrict__ Bhi, const bf16* __restrict__ Blo,
              const float* __restrict__ bias, float* __restrict__ fout,
              bf16* __restrict__ thi, bf16* __restrict__ tlo){
    __shared__ __align__(16) bf16 sA[2][128*ASTR];
    __shared__ __align__(16) bf16 sB[2][128*ASTR];

    const int tid = threadIdx.x, wid = tid >> 5, l = tid & 31;
    const int m0 = blockIdx.x*128, n0 = blockIdx.y*128;
    const int wm = wid >> 2, wn = wid & 3;    // warp tile (wm*64, wn*32)

    const uint32_t aB = smem_u32(sA), bB = smem_u32(sB);

    // segment operand pairs: Ah*Bh + Al*Bh + Ah*Bl
    const bf16* Asegs[3] = {Ahi, Alo, Ahi};
    const bf16* Bsegs[3] = {Bhi, Bhi, Blo};

    // loader indexing: 512 16B-chunks per operand per stage, 2 per thread
    const int lrow0 = tid >> 2;               // 0..63
    const int lcol  = (tid & 3) << 3;         // bf16 col {0,8,16,24}
    const int NIT = 3*(DD/32);                // 120

    auto load_tile = [&](int it, int st){
        int seg = it / (DD/32);
        int kt  = (it % (DD/32)) * 32;
        const bf16* As = Asegs[seg];
        const bf16* Bs = Bsegs[seg];
        uint32_t sa = aB + st*10240u, sb = bB + st*10240u;
        #pragma unroll
        for (int i=0;i<2;i++){
            int row = lrow0 + i*64;
            cpa16(sa + (uint32_t)(row*ASTR + lcol)*2u, As + (size_t)(m0+row)*DD + kt + lcol);
            cpa16(sb + (uint32_t)(row*ASTR + lcol)*2u, Bs + (size_t)(n0+row)*DD + kt + lcol);
        }
    };

    float acc[4][4][4];
    #pragma unroll
    for (int i=0;i<4;i++)
        #pragma unroll
        for (int j=0;j<4;j++)
            #pragma unroll
            for (int k=0;k<4;k++) acc[i][j][k]=0.f;

    // per-lane ldmatrix address pieces (bytes)
    const uint32_t aLane = (uint32_t)(((l & 15)*ASTR + ((l >> 4) << 3)) * 2);
    const uint32_t bLane = (uint32_t)((((l & 7) + ((l >> 4) << 3))*ASTR + (((l >> 3) & 1) << 3)) * 2);

    load_tile(0, 0);
    cpa_commit();

    for (int it=0; it<NIT; it++){
        int st = it & 1;
        if (it + 1 < NIT) load_tile(it+1, (it+1)&1);
        cpa_commit();
        cpa_wait1();
        __syncthreads();

        uint32_t saw = aB + st*10240u + (uint32_t)(wm*64*ASTR)*2u + aLane;
        uint32_t sbw = bB + st*10240u + (uint32_t)(wn*32*ASTR)*2u + bLane;
        #pragma unroll
        for (int k16=0; k16<2; k16++){
            uint32_t a[4][4], b[2][4];
            #pragma unroll
            for (int mi=0;mi<4;mi++)
                ldsm4(a[mi], saw + (uint32_t)(mi*16*ASTR)*2u + k16*32u);
            #pragma unroll
            for (int nj=0;nj<2;nj++)
                ldsm4(b[nj], sbw + (uint32_t)(nj*16*ASTR)*2u + k16*32u);
            #pragma unroll
            for (int mi=0;mi<4;mi++){
                #pragma unroll
                for (int ni=0;ni<4;ni++){
                    int nj = ni >> 1, half = ni & 1;
                    mma16816(acc[mi][ni], a[mi], b[nj][half*2], b[nj][half*2+1]);
                }
            }
        }
        __syncthreads();
    }

    // ---------------- epilogue ----------------
    const int mwarp = m0 + wm*64, nwarp = n0 + wn*32;
    const int rl = l >> 2, cl = (l & 3) << 1;
    #pragma unroll
    for (int mi=0;mi<4;mi++){
        #pragma unroll
        for (int ni=0;ni<4;ni++){
            const float* c = acc[mi][ni];
            int col = nwarp + ni*8 + cl;
            #pragma unroll
            for (int h=0; h<2; h++){
                int m = mwarp + mi*16 + rl + h*8;
                float v0 = c[h*2], v1 = c[h*2+1];
                if (MODE == 0){
                    if (col < DD){
                        float s0 = silu_f(v0), s1 = silu_f(v1);
                        bf16 h0,l0,h1,l1; hilo(s0,h0,l0); hilo(s1,h1,l1);
                        __nv_bfloat162 hh; hh.x=h0; hh.y=h1;
                        __nv_bfloat162 ll; ll.x=l0; ll.y=l1;
                        *(__nv_bfloat162*)(thi + (size_t)m*DD + col) = hh;
                        *(__nv_bfloat162*)(tlo + (size_t)m*DD + col) = ll;
                    } else {
                        float2 o; o.x = silu_f(v0); o.y = silu_f(v1);
                        *(float2*)(fout + (size_t)m*DD + (col - DD)) = o;
                    }
                } else if (MODE == 1){
                    float2 o; o.x = v0 + __ldg(bias + col); o.y = v1 + __ldg(bias + col + 1);
                    int ro = ((m & (TT-1)) << 4) | (m >> 11);
                    *(float2*)(fout + (size_t)ro*DD + col) = o;
                } else {
                    int bb = m & 15, tt = m >> 4;
                    float2 o; o.x = v0; o.y = v1;
                    *(float2*)(fout + (size_t)bb*TT*DD + (size_t)tt*DD + col) = o;
                }
            }
        }
    }
}

// ============================================================================
// Persistent recurrence (unchanged math from R3). Epilogue writes h*silu(z)
// as row-major bf16 hi/lo (rows t*B+b) for GEMM3.
// ============================================================================
extern __shared__ float smem_dyn[];
__global__ __launch_bounds__(256,1)
void recur_kernel(const float* __restrict__ W_h, const float* __restrict__ xpre,
                  const float* __restrict__ sz,
                  bf16* __restrict__ ot_hi, bf16* __restrict__ ot_lo,
                  float* __restrict__ dout_h){
    float* Wsh = smem_dyn;              // [10][1280]
    float* red = smem_dyn + ESL*DD;     // [4][REDS]
    const int tid = threadIdx.x;
    const int e0  = blockIdx.x * ESL;

    {
        const float4* Wsrc = (const float4*)(W_h + (size_t)e0*DD);
        float4* Wdst = (float4*)Wsh;
        for (int idx = tid; idx < ESL*DD/4; idx += 256) Wdst[idx] = Wsrc[idx];
    }
    __syncthreads();

    const int w  = tid >> 5, l = tid & 31;
    const int kq = l & 7;
    const int bq = l >> 3;
    const int q  = w >> 1;
    const int b  = (w & 1)*4 + bq;
    const int kbase = q*320 + kq*4;
    const int rb = tid / 10, re = tid - rb*10;
    const bool epi = (tid < 160);

    for (int t=0; t<TT; t++){
        float xp = 0.f, zz = 0.f;
        if (epi){
            xp = xpre[(size_t)(t*BB + rb)*DD + e0 + re];
            zz = sz[(size_t)rb*TT*DD + (size_t)t*DD + e0 + re];
        }

        const float* hb = g_h[t&1];
        const float* hp0 = hb + b*DD + kbase;
        const float* hp1 = hb + (b+8)*DD + kbase;
        ull acc0[10], acc1[10];
        #pragma unroll
        for (int e=0;e<10;e++){ acc0[e]=0ULL; acc1[e]=0ULL; }

        #pragma unroll 2
        for (int it=0; it<10; it++){
            float4 h0 = __ldcg((const float4*)(hp0 + it*32));
            float4 h1 = __ldcg((const float4*)(hp1 + it*32));
            ull p0a = pkxy(h0.x, h0.y), p0b = pkxy(h0.z, h0.w);
            ull p1a = pkxy(h1.x, h1.y), p1b = pkxy(h1.z, h1.w);
            const float* wp = Wsh + kbase + it*32;
            #pragma unroll
            for (int e=0;e<10;e++){
                ulonglong2 wv = *(const ulonglong2*)(wp + e*DD);
                acc0[e] = ffma2(p0a, wv.x, acc0[e]);
                acc0[e] = ffma2(p0b, wv.y, acc0[e]);
                acc1[e] = ffma2(p1a, wv.x, acc1[e]);
                acc1[e] = ffma2(p1b, wv.y, acc1[e]);
            }
        }

        float s0[10], s1[10];
        #pragma unroll
        for (int e=0;e<10;e++){ s0[e] = hadd(acc0[e]); s1[e] = hadd(acc1[e]); }
        #pragma unroll
        for (int d=1; d<8; d<<=1){
            #pragma unroll
            for (int e=0;e<10;e++){
                s0[e] += __shfl_xor_sync(0xffffffffu, s0[e], d);
                s1[e] += __shfl_xor_sync(0xffffffffu, s1[e], d);
            }
        }
        if (kq == 0){
            float* rp0 = red + q*REDS + b*10;
            float* rp1 = red + q*REDS + (b+8)*10;
            #pragma unroll
            for (int e=0;e<10;e+=2){
                *(float2*)(rp0+e) = make_float2(s0[e], s0[e+1]);
                *(float2*)(rp1+e) = make_float2(s1[e], s1[e+1]);
            }
        }
        __syncthreads();

        if (epi){
            float s = red[0*REDS+tid] + red[1*REDS+tid] + red[2*REDS+tid] + red[3*REDS+tid];
            float h = tanhf(xp + s);
            __stcg(&g_h[(t+1)&1][rb*DD + e0 + re], h);
            float op = h * zz;
            size_t oidx = (size_t)(t*BB + rb)*DD + e0 + re;
            bf16 hi, lo; hilo(op, hi, lo);
            ot_hi[oidx] = hi;
            ot_lo[oidx] = lo;
            if (dout_h != nullptr && t == TT-1) dout_h[rb*DD + e0 + re] = h;
        }
        __threadfence();
        __syncthreads();
        if (tid == 0){
            ull old = atomicAdd(&g_bar, 1ULL);
            ull target = (ull)(t+1) * (ull)GCTA;
            if (old + 1ULL == target){
                __threadfence();
                atomicExch(&g_flag, target);
            } else {
                long long guard = 0;
                while (true){
                    ull f;
                    asm volatile("ld.global.cg.u64 %0, [%1];" : "=l"(f) : "l"(&g_flag));
                    if (f >= target) break;
                    if (++guard > 4000000LL) break;   // anti-hang bailout
                    __nanosleep(20);
                }
            }
            __threadfence();
        }
        __syncthreads();
    }
}

// ============================================================================
extern "C" void kernel_launch(void* const* d_in, const int* in_sizes, int n_in,
                              void* d_out, int out_size){
    const float* x     = (const float*)d_in[0];   // (16,2048,1280)
    const float* W_in  = (const float*)d_in[1];   // (2560,1280)
    const float* W_out = (const float*)d_in[2];   // (1280,1280)
    const float* W_x   = (const float*)d_in[3];   // (1280,1280)
    const float* W_h   = (const float*)d_in[4];   // (1280,1280)
    const float* bias  = (const float*)d_in[5];   // (1280,)
    float* out = (float*)d_out;

    const int recur_smem = (ESL*DD + 4*REDS) * 4;          // 53888
    cudaFuncSetAttribute(recur_kernel, cudaFuncAttributeMaxDynamicSharedMemorySize, recur_smem);

    float* dout_h = (out_size >= BT*DD + BB*DD) ? (out + (size_t)BT*DD) : nullptr;

    float *sz_p, *xpre_p;
    bf16 *xt_hi, *xt_lo, *pt_hi, *pt_lo, *ot_hi, *ot_lo;
    bf16 *wi_hi, *wi_lo, *wx_hi, *wx_lo, *wo_hi, *wo_lo;
    cudaGetSymbolAddress((void**)&sz_p,   g_sz);
    cudaGetSymbolAddress((void**)&xpre_p, g_xpre);
    cudaGetSymbolAddress((void**)&xt_hi,  g_xt_hi);
    cudaGetSymbolAddress((void**)&xt_lo,  g_xt_lo);
    cudaGetSymbolAddress((void**)&pt_hi,  g_pt_hi);
    cudaGetSymbolAddress((void**)&pt_lo,  g_pt_lo);
    cudaGetSymbolAddress((void**)&ot_hi,  g_ot_hi);
    cudaGetSymbolAddress((void**)&ot_lo,  g_ot_lo);
    cudaGetSymbolAddress((void**)&wi_hi,  g_wi_hi);
    cudaGetSymbolAddress((void**)&wi_lo,  g_wi_lo);
    cudaGetSymbolAddress((void**)&wx_hi,  g_wx_hi);
    cudaGetSymbolAddress((void**)&wx_lo,  g_wx_lo);
    cudaGetSymbolAddress((void**)&wo_hi,  g_wo_hi);
    cudaGetSymbolAddress((void**)&wo_lo,  g_wo_lo);

    reset_kernel<<<80, 256>>>();

    // fp32 -> bf16 hi/lo row-major
    convert_hilo<<<(BT*DD/4 + 255)/256, 256>>>(x,     xt_hi, xt_lo, BT*DD/4);
    convert_hilo<<<(2*DD*DD/4 + 255)/256, 256>>>(W_in,  wi_hi, wi_lo, 2*DD*DD/4);
    convert_hilo<<<(DD*DD/4 + 255)/256, 256>>>(W_x,   wx_hi, wx_lo, DD*DD/4);
    convert_hilo<<<(DD*DD/4 + 255)/256, 256>>>(W_out, wo_hi, wo_lo, DD*DD/4);

    // GEMM1: xz = x @ W_in^T; silu; xproj -> pt hi/lo, silu(z) -> g_sz fp32
    gemm_mma<0><<<dim3(BT/128, (2*DD)/128), 256>>>(xt_hi, xt_lo, wi_hi, wi_lo,
                                                   nullptr, sz_p, pt_hi, pt_lo);

    // GEMM2: x_pre = silu(xproj) @ W_x^T + b -> fp32 (T,B,D)
    gemm_mma<1><<<dim3(BT/128, DD/128), 256>>>(pt_hi, pt_lo, wx_hi, wx_lo,
                                               bias, xpre_p, nullptr, nullptr);

    // Recurrence (persistent, 2048 steps); writes GEMM3 A hi/lo
    recur_kernel<<<GCTA, 256, recur_smem>>>(W_h, xpre_p, sz_p, ot_hi, ot_lo, dout_h);

    // GEMM3: out = out_pre @ W_out^T -> d_out (B,T,D)
    gemm_mma<2><<<dim3(BT/128, DD/128), 256>>>(ot_hi, ot_lo, wo_hi, wo_lo,
                                               nullptr, out, nullptr, nullptr);
}

// round 6
// speedup vs baseline: 1.3553x; 1.0166x over previous
#include <cuda_runtime.h>
#include <cuda_bf16.h>
#include <math.h>
#include <stdint.h>

typedef unsigned long long ull;
typedef __nv_bfloat16 bf16;

#define BB 16
#define TT 2048
#define DD 1280
#define BT (BB*TT)          // 32768
#define ASTR 40             // gemm smem row stride (bf16)

#define NGRP 4              // independent recurrence groups
#define GCTAS 32            // CTAs per group
#define GB 4                // batches per group
#define EPC 40              // e-rows of W_h per CTA

// ---------------- scratch (static __device__) ----------------
__device__ float g_sz[BT*DD];        // silu(z), fp32, rows b*T+t
__device__ float g_xpre[BT*DD];      // x_pre,   fp32, rows t*B+b
__device__ float g_h[2][BB*DD];
__device__ ull   g_bars[NGRP];
__device__ ull   g_flags[NGRP];

// bf16 hi/lo row-major operands
__device__ bf16 g_xt_hi[BT*DD],  g_xt_lo[BT*DD];     // x
__device__ bf16 g_pt_hi[BT*DD],  g_pt_lo[BT*DD];     // silu(xproj)
__device__ bf16 g_ot_hi[BT*DD],  g_ot_lo[BT*DD];     // h*silu(z), rows t*B+b
__device__ bf16 g_wi_hi[2*DD*DD], g_wi_lo[2*DD*DD];  // W_in
__device__ bf16 g_wx_hi[DD*DD],   g_wx_lo[DD*DD];    // W_x
__device__ bf16 g_wo_hi[DD*DD],   g_wo_lo[DD*DD];    // W_out

// ---------------- helpers ----------------
__device__ __forceinline__ ull ffma2(ull a, ull b, ull c){
    ull d; asm("fma.rn.f32x2 %0, %1, %2, %3;" : "=l"(d) : "l"(a), "l"(b), "l"(c)); return d;
}
__device__ __forceinline__ ull pkxy(float x, float y){
    ull d; asm("mov.b64 %0, {%1, %2};" : "=l"(d) : "f"(x), "f"(y)); return d;
}
__device__ __forceinline__ float2 unpk(ull v){
    float2 r; asm("mov.b64 {%0, %1}, %2;" : "=f"(r.x), "=f"(r.y) : "l"(v)); return r;
}
__device__ __forceinline__ float hadd(ull v){ float2 f = unpk(v); return f.x + f.y; }
__device__ __forceinline__ float silu_f(float v){ return v * (1.f/(1.f + __expf(-v))); }
__device__ __forceinline__ uint32_t smem_u32(const void* p){
    uint32_t a; asm("{ .reg .u64 t; cvta.to.shared.u64 t, %1; cvt.u32.u64 %0, t; }" : "=r"(a) : "l"(p));
    return a;
}
__device__ __forceinline__ void cpa16(uint32_t s, const void* g){
    asm volatile("cp.async.cg.shared.global [%0], [%1], 16;" :: "r"(s), "l"(g));
}
__device__ __forceinline__ void cpa_commit(){ asm volatile("cp.async.commit_group;"); }
__device__ __forceinline__ void cpa_wait1(){ asm volatile("cp.async.wait_group 1;"); }

__device__ __forceinline__ void ldsm4(uint32_t* r, uint32_t addr){
    asm volatile("ldmatrix.sync.aligned.m8n8.x4.shared.b16 {%0,%1,%2,%3}, [%4];"
        : "=r"(r[0]), "=r"(r[1]), "=r"(r[2]), "=r"(r[3]) : "r"(addr));
}
__device__ __forceinline__ void mma16816(float* c, const uint32_t* a, uint32_t b0, uint32_t b1){
    asm volatile("mma.sync.aligned.m16n8k16.row.col.f32.bf16.bf16.f32 "
        "{%0,%1,%2,%3}, {%4,%5,%6,%7}, {%8,%9}, {%0,%1,%2,%3};"
        : "+f"(c[0]), "+f"(c[1]), "+f"(c[2]), "+f"(c[3])
        : "r"(a[0]), "r"(a[1]), "r"(a[2]), "r"(a[3]), "r"(b0), "r"(b1));
}
__device__ __forceinline__ void hilo(float v, bf16& h, bf16& l){
    h = __float2bfloat16(v);
    l = __float2bfloat16(v - __bfloat162float(h));
}

// ---------------- reset ----------------
__global__ void reset_kernel(){
    int i = blockIdx.x*blockDim.x + threadIdx.x;
    if (i < NGRP){ g_bars[i] = 0ULL; g_flags[i] = 0ULL; }
    if (i < BB*DD) g_h[0][i] = 0.f;
}

// ---------------- fp32 -> bf16 hi/lo ----------------
__global__ void convert_hilo(const float* __restrict__ src, bf16* __restrict__ hi,
                             bf16* __restrict__ lo, int n4){
    int i = blockIdx.x*blockDim.x + threadIdx.x;
    if (i >= n4) return;
    float4 v = *(const float4*)(src + (size_t)i*4);
    bf16 h0,l0,h1,l1,h2,l2,h3,l3;
    hilo(v.x,h0,l0); hilo(v.y,h1,l1); hilo(v.z,h2,l2); hilo(v.w,h3,l3);
    __nv_bfloat162 hh0; hh0.x=h0; hh0.y=h1;
    __nv_bfloat162 hh1; hh1.x=h2; hh1.y=h3;
    __nv_bfloat162 ll0; ll0.x=l0; ll0.y=l1;
    __nv_bfloat162 ll1; ll1.x=l2; ll1.y=l3;
    *(__nv_bfloat162*)(hi + (size_t)i*4)     = hh0;
    *(__nv_bfloat162*)(hi + (size_t)i*4 + 2) = hh1;
    *(__nv_bfloat162*)(lo + (size_t)i*4)     = ll0;
    *(__nv_bfloat162*)(lo + (size_t)i*4 + 2) = ll1;
}

// ============================================================================
// bf16 mma.sync GEMM with 3-term hi/lo split (unchanged from R5 pass).
// ============================================================================
template<int MODE>
__global__ __launch_bounds__(256,2)
void gemm_mma(const bf16* __restrict__ Ahi, const bf16* __restrict__ Alo,
              const bf16* __restrict__ Bhi, const bf16* __restrict__ Blo,
              const float* __restrict__ bias, float* __restrict__ fout,
              bf16* __restrict__ thi, bf16* __restrict__ tlo){
    __shared__ __align__(16) bf16 sA[2][128*ASTR];
    __shared__ __align__(16) bf16 sB[2][128*ASTR];

    const int tid = threadIdx.x, wid = tid >> 5, l = tid & 31;
    const int m0 = blockIdx.x*128, n0 = blockIdx.y*128;
    const int wm = wid >> 2, wn = wid & 3;

    const uint32_t aB = smem_u32(sA), bB = smem_u32(sB);

    const bf16* Asegs[3] = {Ahi, Alo, Ahi};
    const bf16* Bsegs[3] = {Bhi, Bhi, Blo};

    const int lrow0 = tid >> 2;
    const int lcol  = (tid & 3) << 3;
    const int NIT = 3*(DD/32);

    auto load_tile = [&](int it, int st){
        int seg = it / (DD/32);
        int kt  = (it % (DD/32)) * 32;
        const bf16* As = Asegs[seg];
        const bf16* Bs = Bsegs[seg];
        uint32_t sa = aB + st*10240u, sb = bB + st*10240u;
        #pragma unroll
        for (int i=0;i<2;i++){
            int row = lrow0 + i*64;
            cpa16(sa + (uint32_t)(row*ASTR + lcol)*2u, As + (size_t)(m0+row)*DD + kt + lcol);
            cpa16(sb + (uint32_t)(row*ASTR + lcol)*2u, Bs + (size_t)(n0+row)*DD + kt + lcol);
        }
    };

    float acc[4][4][4];
    #pragma unroll
    for (int i=0;i<4;i++)
        #pragma unroll
        for (int j=0;j<4;j++)
            #pragma unroll
            for (int k=0;k<4;k++) acc[i][j][k]=0.f;

    const uint32_t aLane = (uint32_t)(((l & 15)*ASTR + ((l >> 4) << 3)) * 2);
    const uint32_t bLane = (uint32_t)((((l & 7) + ((l >> 4) << 3))*ASTR + (((l >> 3) & 1) << 3)) * 2);

    load_tile(0, 0);
    cpa_commit();

    for (int it=0; it<NIT; it++){
        int st = it & 1;
        if (it + 1 < NIT) load_tile(it+1, (it+1)&1);
        cpa_commit();
        cpa_wait1();
        __syncthreads();

        uint32_t saw = aB + st*10240u + (uint32_t)(wm*64*ASTR)*2u + aLane;
        uint32_t sbw = bB + st*10240u + (uint32_t)(wn*32*ASTR)*2u + bLane;
        #pragma unroll
        for (int k16=0; k16<2; k16++){
            uint32_t a[4][4], b[2][4];
            #pragma unroll
            for (int mi=0;mi<4;mi++)
                ldsm4(a[mi], saw + (uint32_t)(mi*16*ASTR)*2u + k16*32u);
            #pragma unroll
            for (int nj=0;nj<2;nj++)
                ldsm4(b[nj], sbw + (uint32_t)(nj*16*ASTR)*2u + k16*32u);
            #pragma unroll
            for (int mi=0;mi<4;mi++){
                #pragma unroll
                for (int ni=0;ni<4;ni++){
                    int nj = ni >> 1, half = ni & 1;
                    mma16816(acc[mi][ni], a[mi], b[nj][half*2], b[nj][half*2+1]);
                }
            }
        }
        __syncthreads();
    }

    const int mwarp = m0 + wm*64, nwarp = n0 + wn*32;
    const int rl = l >> 2, cl = (l & 3) << 1;
    #pragma unroll
    for (int mi=0;mi<4;mi++){
        #pragma unroll
        for (int ni=0;ni<4;ni++){
            const float* c = acc[mi][ni];
            int col = nwarp + ni*8 + cl;
            #pragma unroll
            for (int h=0; h<2; h++){
                int m = mwarp + mi*16 + rl + h*8;
                float v0 = c[h*2], v1 = c[h*2+1];
                if (MODE == 0){
                    if (col < DD){
                        float s0 = silu_f(v0), s1 = silu_f(v1);
                        bf16 h0,l0,h1,l1; hilo(s0,h0,l0); hilo(s1,h1,l1);
                        __nv_bfloat162 hh; hh.x=h0; hh.y=h1;
                        __nv_bfloat162 ll; ll.x=l0; ll.y=l1;
                        *(__nv_bfloat162*)(thi + (size_t)m*DD + col) = hh;
                        *(__nv_bfloat162*)(tlo + (size_t)m*DD + col) = ll;
                    } else {
                        float2 o; o.x = silu_f(v0); o.y = silu_f(v1);
                        *(float2*)(fout + (size_t)m*DD + (col - DD)) = o;
                    }
                } else if (MODE == 1){
                    float2 o; o.x = v0 + __ldg(bias + col); o.y = v1 + __ldg(bias + col + 1);
                    int ro = ((m & (TT-1)) << 4) | (m >> 11);
                    *(float2*)(fout + (size_t)ro*DD + col) = o;
                } else {
                    int bb = m & 15, tt = m >> 4;
                    float2 o; o.x = v0; o.y = v1;
                    *(float2*)(fout + (size_t)bb*TT*DD + (size_t)tt*DD + col) = o;
                }
            }
        }
    }
}

// ============================================================================
// Recurrence v2: 4 INDEPENDENT groups x 32 CTAs. Group g owns batches 4g..4g+3
// (batch recurrences are independent -> no cross-group sync). CTA c holds
// W_h rows [c*40, c*40+40) in SMEM fp32 (204.8KB, 1 CTA/SM).
// Warp w: e-rows w*5..w*5+4. Lane: o=l>>3 (p=o&1 batch-pair, kh=o>>1 k-half),
// kq=l&7. Per iter: 2 LDG.128 (h, contiguous per octet) + 5 LDS.128 (W,
// conflict-free broadcast) + 20 FFMA2 -> FMA-bound. k-reduce via warp shfl
// (xor 1,2,4,16). Per-group flag-release barrier (32 arrivals).
// ============================================================================
extern __shared__ float smem_dyn[];
__global__ __launch_bounds__(256,1)
void recur_kernel(const float* __restrict__ W_h, const float* __restrict__ xpre,
                  const float* __restrict__ sz,
                  bf16* __restrict__ ot_hi, bf16* __restrict__ ot_lo,
                  float* __restrict__ dout_h){
    float* Wsh = smem_dyn;               // [40][1280]
    float* red = smem_dyn + EPC*DD;      // [8 warps][20]
    const int tid = threadIdx.x;
    const int g   = blockIdx.x >> 5;     // group 0..3
    const int c   = blockIdx.x & 31;     // CTA in group
    const int e0  = c*EPC;
    const int b0  = g*GB;

    {   // load W_h slice (rows e0..e0+39 contiguous)
        const float4* Wsrc = (const float4*)(W_h + (size_t)e0*DD);
        float4* Wdst = (float4*)Wsh;
        for (int idx = tid; idx < EPC*DD/4; idx += 256) Wdst[idx] = Wsrc[idx];
    }
    __syncthreads();

    const int w  = tid >> 5, l = tid & 31;
    const int kq = l & 7;
    const int o  = l >> 3;
    const int p  = o & 1;                 // batch pair: batches b0+2p, b0+2p+1
    const int kh = o >> 1;                // k half (640 each)
    const int kbase = kh*640 + kq*4;

    // epilogue mapping: tid<160 -> (bl, eg)
    const int bl = tid / EPC;             // 0..3
    const int eg = tid - bl*EPC;          // 0..39
    const bool epi = (tid < 160);
    const int rw = eg / 5, re5 = eg - rw*5;

    ull* bars  = &g_bars[g];
    ull* flags = &g_flags[g];

    for (int t=0; t<TT; t++){
        float xp = 0.f, zz = 0.f;
        if (epi){
            xp = xpre[(size_t)(t*BB + b0 + bl)*DD + e0 + eg];
            zz = sz[(size_t)(b0 + bl)*TT*DD + (size_t)t*DD + e0 + eg];
        }

        const float* hp0 = g_h[t&1] + (size_t)(b0 + 2*p)*DD + kbase;
        const float* hp1 = hp0 + DD;
        ull acc0[5], acc1[5];
        #pragma unroll
        for (int e=0;e<5;e++){ acc0[e]=0ULL; acc1[e]=0ULL; }

        const float* wp0 = Wsh + (size_t)(w*5)*DD + kbase;
        #pragma unroll 4
        for (int it=0; it<20; it++){
            float4 h0 = __ldcg((const float4*)(hp0 + it*32));
            float4 h1 = __ldcg((const float4*)(hp1 + it*32));
            ull a01 = pkxy(h0.x, h0.y), a23 = pkxy(h0.z, h0.w);
            ull b01 = pkxy(h1.x, h1.y), b23 = pkxy(h1.z, h1.w);
            const float* wp = wp0 + it*32;
            #pragma unroll
            for (int e=0;e<5;e++){
                ulonglong2 wv = *(const ulonglong2*)(wp + e*DD);
                acc0[e] = ffma2(a01, wv.x, acc0[e]);
                acc0[e] = ffma2(a23, wv.y, acc0[e]);
                acc1[e] = ffma2(b01, wv.x, acc1[e]);
                acc1[e] = ffma2(b23, wv.y, acc1[e]);
            }
        }

        float s0[5], s1[5];
        #pragma unroll
        for (int e=0;e<5;e++){ s0[e] = hadd(acc0[e]); s1[e] = hadd(acc1[e]); }
        #pragma unroll
        for (int st=0; st<4; st++){
            const int msk = (st<3) ? (1<<st) : 16;   // xor 1,2,4,16 (kq bits + khalf bit)
            #pragma unroll
            for (int e=0;e<5;e++){
                s0[e] += __shfl_xor_sync(0xffffffffu, s0[e], msk);
                s1[e] += __shfl_xor_sync(0xffffffffu, s1[e], msk);
            }
        }
        if ((l & 0x17) == 0){   // lanes 0 (p=0) and 8 (p=1)
            float* rp = red + w*20 + 2*p*5;
            #pragma unroll
            for (int e=0;e<5;e++){ rp[e] = s0[e]; rp[5+e] = s1[e]; }
        }
        __syncthreads();

        if (epi){
            float ssum = red[rw*20 + bl*5 + re5];
            float h = tanhf(xp + ssum);
            __stcg(&g_h[(t+1)&1][(size_t)(b0 + bl)*DD + e0 + eg], h);
            float op = h * zz;
            size_t oidx = (size_t)(t*BB + b0 + bl)*DD + e0 + eg;
            bf16 hi, lo; hilo(op, hi, lo);
            ot_hi[oidx] = hi;
            ot_lo[oidx] = lo;
            if (dout_h != nullptr && t == TT-1) dout_h[(size_t)(b0 + bl)*DD + e0 + eg] = h;
        }
        __threadfence();
        __syncthreads();
        if (tid == 0){
            ull old = atomicAdd(bars, 1ULL);
            ull target = (ull)(t+1) * (ull)GCTAS;
            if (old + 1ULL == target){
                __threadfence();
                atomicExch(flags, target);
            } else {
                long long guard = 0;
                while (true){
                    ull f;
                    asm volatile("ld.global.cg.u64 %0, [%1];" : "=l"(f) : "l"(flags));
                    if (f >= target) break;
                    if (++guard > 8000000LL) break;   // anti-hang bailout
                    __nanosleep(20);
                }
            }
            __threadfence();
        }
        __syncthreads();
    }
}

// ============================================================================
extern "C" void kernel_launch(void* const* d_in, const int* in_sizes, int n_in,
                              void* d_out, int out_size){
    const float* x     = (const float*)d_in[0];
    const float* W_in  = (const float*)d_in[1];
    const float* W_out = (const float*)d_in[2];
    const float* W_x   = (const float*)d_in[3];
    const float* W_h   = (const float*)d_in[4];
    const float* bias  = (const float*)d_in[5];
    float* out = (float*)d_out;

    const int recur_smem = (EPC*DD + 8*20 + 32) * 4;       // ~205.6 KB
    cudaFuncSetAttribute(recur_kernel, cudaFuncAttributeMaxDynamicSharedMemorySize, recur_smem);

    float* dout_h = (out_size >= BT*DD + BB*DD) ? (out + (size_t)BT*DD) : nullptr;

    float *sz_p, *xpre_p;
    bf16 *xt_hi, *xt_lo, *pt_hi, *pt_lo, *ot_hi, *ot_lo;
    bf16 *wi_hi, *wi_lo, *wx_hi, *wx_lo, *wo_hi, *wo_lo;
    cudaGetSymbolAddress((void**)&sz_p,   g_sz);
    cudaGetSymbolAddress((void**)&xpre_p, g_xpre);
    cudaGetSymbolAddress((void**)&xt_hi,  g_xt_hi);
    cudaGetSymbolAddress((void**)&xt_lo,  g_xt_lo);
    cudaGetSymbolAddress((void**)&pt_hi,  g_pt_hi);
    cudaGetSymbolAddress((void**)&pt_lo,  g_pt_lo);
    cudaGetSymbolAddress((void**)&ot_hi,  g_ot_hi);
    cudaGetSymbolAddress((void**)&ot_lo,  g_ot_lo);
    cudaGetSymbolAddress((void**)&wi_hi,  g_wi_hi);
    cudaGetSymbolAddress((void**)&wi_lo,  g_wi_lo);
    cudaGetSymbolAddress((void**)&wx_hi,  g_wx_hi);
    cudaGetSymbolAddress((void**)&wx_lo,  g_wx_lo);
    cudaGetSymbolAddress((void**)&wo_hi,  g_wo_hi);
    cudaGetSymbolAddress((void**)&wo_lo,  g_wo_lo);

    reset_kernel<<<80, 256>>>();

    convert_hilo<<<(BT*DD/4 + 255)/256, 256>>>(x,     xt_hi, xt_lo, BT*DD/4);
    convert_hilo<<<(2*DD*DD/4 + 255)/256, 256>>>(W_in,  wi_hi, wi_lo, 2*DD*DD/4);
    convert_hilo<<<(DD*DD/4 + 255)/256, 256>>>(W_x,   wx_hi, wx_lo, DD*DD/4);
    convert_hilo<<<(DD*DD/4 + 255)/256, 256>>>(W_out, wo_hi, wo_lo, DD*DD/4);

    gemm_mma<0><<<dim3(BT/128, (2*DD)/128), 256>>>(xt_hi, xt_lo, wi_hi, wi_lo,
                                                   nullptr, sz_p, pt_hi, pt_lo);

    gemm_mma<1><<<dim3(BT/128, DD/128), 256>>>(pt_hi, pt_lo, wx_hi, wx_lo,
                                               bias, xpre_p, nullptr, nullptr);

    recur_kernel<<<NGRP*GCTAS, 256, recur_smem>>>(W_h, xpre_p, sz_p, ot_hi, ot_lo, dout_h);

    gemm_mma<2><<<dim3(BT/128, DD/128), 256>>>(ot_hi, ot_lo, wo_hi, wo_lo,
                                               nullptr, out, nullptr, nullptr);
}

// round 7
// speedup vs baseline: 1.4937x; 1.1021x over previous
#include <cuda_runtime.h>
#include <cuda_bf16.h>
#include <math.h>
#include <stdint.h>

typedef unsigned long long ull;
typedef __nv_bfloat16 bf16;

#define BB 16
#define TT 2048
#define DD 1280
#define BT (BB*TT)          // 32768
#define ASTR 40             // gemm smem row stride (bf16)

#define NGRP 4              // independent recurrence groups
#define GCTAS 32            // CTAs per group
#define GB 4                // batches per group
#define EPC 40              // e-rows of W_h per CTA

// ---------------- scratch (static __device__) ----------------
__device__ float g_sz[BT*DD];        // silu(z), fp32, rows b*T+t
__device__ float g_xpre[BT*DD];      // x_pre,   fp32, rows t*B+b
__device__ float g_h[2][BB*DD];
__device__ uint32_t g_flagv[NGRP][GCTAS][32];   // per-CTA release flags (128B apart)

// bf16 hi/lo row-major operands
__device__ bf16 g_xt_hi[BT*DD],  g_xt_lo[BT*DD];     // x
__device__ bf16 g_pt_hi[BT*DD],  g_pt_lo[BT*DD];     // silu(xproj)
__device__ bf16 g_ot_hi[BT*DD],  g_ot_lo[BT*DD];     // h*silu(z), rows t*B+b
__device__ bf16 g_wi_hi[2*DD*DD], g_wi_lo[2*DD*DD];  // W_in
__device__ bf16 g_wx_hi[DD*DD],   g_wx_lo[DD*DD];    // W_x
__device__ bf16 g_wo_hi[DD*DD],   g_wo_lo[DD*DD];    // W_out

// ---------------- helpers ----------------
__device__ __forceinline__ ull ffma2(ull a, ull b, ull c){
    ull d; asm("fma.rn.f32x2 %0, %1, %2, %3;" : "=l"(d) : "l"(a), "l"(b), "l"(c)); return d;
}
__device__ __forceinline__ ull pkxy(float x, float y){
    ull d; asm("mov.b64 %0, {%1, %2};" : "=l"(d) : "f"(x), "f"(y)); return d;
}
__device__ __forceinline__ float2 unpk(ull v){
    float2 r; asm("mov.b64 {%0, %1}, %2;" : "=f"(r.x), "=f"(r.y) : "l"(v)); return r;
}
__device__ __forceinline__ float hadd(ull v){ float2 f = unpk(v); return f.x + f.y; }
__device__ __forceinline__ float silu_f(float v){ return v * (1.f/(1.f + __expf(-v))); }
__device__ __forceinline__ float tanh_fast(float x){
    float c = fminf(fmaxf(x, -12.f), 12.f);
    float e = __expf(2.f*c);
    return __fdividef(e - 1.f, e + 1.f);
}
__device__ __forceinline__ uint32_t smem_u32(const void* p){
    uint32_t a; asm("{ .reg .u64 t; cvta.to.shared.u64 t, %1; cvt.u32.u64 %0, t; }" : "=r"(a) : "l"(p));
    return a;
}
__device__ __forceinline__ void st_release_u32(uint32_t* p, uint32_t v){
    asm volatile("st.release.gpu.global.u32 [%0], %1;" :: "l"(p), "r"(v) : "memory");
}
__device__ __forceinline__ uint32_t ld_acquire_u32(const uint32_t* p){
    uint32_t v;
    asm volatile("ld.acquire.gpu.global.u32 %0, [%1];" : "=r"(v) : "l"(p) : "memory");
    return v;
}
__device__ __forceinline__ void cpa16(uint32_t s, const void* g){
    asm volatile("cp.async.cg.shared.global [%0], [%1], 16;" :: "r"(s), "l"(g));
}
__device__ __forceinline__ void cpa_commit(){ asm volatile("cp.async.commit_group;"); }
__device__ __forceinline__ void cpa_wait1(){ asm volatile("cp.async.wait_group 1;"); }

__device__ __forceinline__ void ldsm4(uint32_t* r, uint32_t addr){
    asm volatile("ldmatrix.sync.aligned.m8n8.x4.shared.b16 {%0,%1,%2,%3}, [%4];"
        : "=r"(r[0]), "=r"(r[1]), "=r"(r[2]), "=r"(r[3]) : "r"(addr));
}
__device__ __forceinline__ void mma16816(float* c, const uint32_t* a, uint32_t b0, uint32_t b1){
    asm volatile("mma.sync.aligned.m16n8k16.row.col.f32.bf16.bf16.f32 "
        "{%0,%1,%2,%3}, {%4,%5,%6,%7}, {%8,%9}, {%0,%1,%2,%3};"
        : "+f"(c[0]), "+f"(c[1]), "+f"(c[2]), "+f"(c[3])
        : "r"(a[0]), "r"(a[1]), "r"(a[2]), "r"(a[3]), "r"(b0), "r"(b1));
}
__device__ __forceinline__ void hilo(float v, bf16& h, bf16& l){
    h = __float2bfloat16(v);
    l = __float2bfloat16(v - __bfloat162float(h));
}

// ---------------- reset ----------------
__global__ void reset_kernel(){
    int i = blockIdx.x*blockDim.x + threadIdx.x;
    if (i < NGRP*GCTAS*32) ((uint32_t*)g_flagv)[i] = 0u;
    if (i < BB*DD) g_h[0][i] = 0.f;
}

// ---------------- fp32 -> bf16 hi/lo ----------------
__global__ void convert_hilo(const float* __restrict__ src, bf16* __restrict__ hi,
                             bf16* __restrict__ lo, int n4){
    int i = blockIdx.x*blockDim.x + threadIdx.x;
    if (i >= n4) return;
    float4 v = *(const float4*)(src + (size_t)i*4);
    bf16 h0,l0,h1,l1,h2,l2,h3,l3;
    hilo(v.x,h0,l0); hilo(v.y,h1,l1); hilo(v.z,h2,l2); hilo(v.w,h3,l3);
    __nv_bfloat162 hh0; hh0.x=h0; hh0.y=h1;
    __nv_bfloat162 hh1; hh1.x=h2; hh1.y=h3;
    __nv_bfloat162 ll0; ll0.x=l0; ll0.y=l1;
    __nv_bfloat162 ll1; ll1.x=l2; ll1.y=l3;
    *(__nv_bfloat162*)(hi + (size_t)i*4)     = hh0;
    *(__nv_bfloat162*)(hi + (size_t)i*4 + 2) = hh1;
    *(__nv_bfloat162*)(lo + (size_t)i*4)     = ll0;
    *(__nv_bfloat162*)(lo + (size_t)i*4 + 2) = ll1;
}

// ============================================================================
// bf16 mma.sync GEMM with 3-term hi/lo split (unchanged, R5/R6-verified).
// ============================================================================
template<int MODE>
__global__ __launch_bounds__(256,2)
void gemm_mma(const bf16* __restrict__ Ahi, const bf16* __restrict__ Alo,
              const bf16* __restrict__ Bhi, const bf16* __restrict__ Blo,
              const float* __restrict__ bias, float* __restrict__ fout,
              bf16* __restrict__ thi, bf16* __restrict__ tlo){
    __shared__ __align__(16) bf16 sA[2][128*ASTR];
    __shared__ __align__(16) bf16 sB[2][128*ASTR];

    const int tid = threadIdx.x, wid = tid >> 5, l = tid & 31;
    const int m0 = blockIdx.x*128, n0 = blockIdx.y*128;
    const int wm = wid >> 2, wn = wid & 3;

    const uint32_t aB = smem_u32(sA), bB = smem_u32(sB);

    const bf16* Asegs[3] = {Ahi, Alo, Ahi};
    const bf16* Bsegs[3] = {Bhi, Bhi, Blo};

    const int lrow0 = tid >> 2;
    const int lcol  = (tid & 3) << 3;
    const int NIT = 3*(DD/32);

    auto load_tile = [&](int it, int st){
        int seg = it / (DD/32);
        int kt  = (it % (DD/32)) * 32;
        const bf16* As = Asegs[seg];
        const bf16* Bs = Bsegs[seg];
        uint32_t sa = aB + st*10240u, sb = bB + st*10240u;
        #pragma unroll
        for (int i=0;i<2;i++){
            int row = lrow0 + i*64;
            cpa16(sa + (uint32_t)(row*ASTR + lcol)*2u, As + (size_t)(m0+row)*DD + kt + lcol);
            cpa16(sb + (uint32_t)(row*ASTR + lcol)*2u, Bs + (size_t)(n0+row)*DD + kt + lcol);
        }
    };

    float acc[4][4][4];
    #pragma unroll
    for (int i=0;i<4;i++)
        #pragma unroll
        for (int j=0;j<4;j++)
            #pragma unroll
            for (int k=0;k<4;k++) acc[i][j][k]=0.f;

    const uint32_t aLane = (uint32_t)(((l & 15)*ASTR + ((l >> 4) << 3)) * 2);
    const uint32_t bLane = (uint32_t)((((l & 7) + ((l >> 4) << 3))*ASTR + (((l >> 3) & 1) << 3)) * 2);

    load_tile(0, 0);
    cpa_commit();

    for (int it=0; it<NIT; it++){
        int st = it & 1;
        if (it + 1 < NIT) load_tile(it+1, (it+1)&1);
        cpa_commit();
        cpa_wait1();
        __syncthreads();

        uint32_t saw = aB + st*10240u + (uint32_t)(wm*64*ASTR)*2u + aLane;
        uint32_t sbw = bB + st*10240u + (uint32_t)(wn*32*ASTR)*2u + bLane;
        #pragma unroll
        for (int k16=0; k16<2; k16++){
            uint32_t a[4][4], b[2][4];
            #pragma unroll
            for (int mi=0;mi<4;mi++)
                ldsm4(a[mi], saw + (uint32_t)(mi*16*ASTR)*2u + k16*32u);
            #pragma unroll
            for (int nj=0;nj<2;nj++)
                ldsm4(b[nj], sbw + (uint32_t)(nj*16*ASTR)*2u + k16*32u);
            #pragma unroll
            for (int mi=0;mi<4;mi++){
                #pragma unroll
                for (int ni=0;ni<4;ni++){
                    int nj = ni >> 1, half = ni & 1;
                    mma16816(acc[mi][ni], a[mi], b[nj][half*2], b[nj][half*2+1]);
                }
            }
        }
        __syncthreads();
    }

    const int mwarp = m0 + wm*64, nwarp = n0 + wn*32;
    const int rl = l >> 2, cl = (l & 3) << 1;
    #pragma unroll
    for (int mi=0;mi<4;mi++){
        #pragma unroll
        for (int ni=0;ni<4;ni++){
            const float* c = acc[mi][ni];
            int col = nwarp + ni*8 + cl;
            #pragma unroll
            for (int h=0; h<2; h++){
                int m = mwarp + mi*16 + rl + h*8;
                float v0 = c[h*2], v1 = c[h*2+1];
                if (MODE == 0){
                    if (col < DD){
                        float s0 = silu_f(v0), s1 = silu_f(v1);
                        bf16 h0,l0,h1,l1; hilo(s0,h0,l0); hilo(s1,h1,l1);
                        __nv_bfloat162 hh; hh.x=h0; hh.y=h1;
                        __nv_bfloat162 ll; ll.x=l0; ll.y=l1;
                        *(__nv_bfloat162*)(thi + (size_t)m*DD + col) = hh;
                        *(__nv_bfloat162*)(tlo + (size_t)m*DD + col) = ll;
                    } else {
                        float2 o; o.x = silu_f(v0); o.y = silu_f(v1);
                        *(float2*)(fout + (size_t)m*DD + (col - DD)) = o;
                    }
                } else if (MODE == 1){
                    float2 o; o.x = v0 + __ldg(bias + col); o.y = v1 + __ldg(bias + col + 1);
                    int ro = ((m & (TT-1)) << 4) | (m >> 11);
                    *(float2*)(fout + (size_t)ro*DD + col) = o;
                } else {
                    int bb = m & 15, tt = m >> 4;
                    float2 o; o.x = v0; o.y = v1;
                    *(float2*)(fout + (size_t)bb*TT*DD + (size_t)tt*DD + col) = o;
                }
            }
        }
    }
}

// ============================================================================
// Recurrence v3: 4 groups x 32 CTAs (group g owns batches 4g..4g+3). CTA c
// holds W_h rows [c*40, c*40+40) in SMEM fp32. Warp w: e-rows w*5..w*5+4.
// Lane l: k-slice {l*4 + 128*it}. Each thread: ALL 4 group batches x 5 e.
// Per iter: 4 indep LDG.128 (h, prefetched one iter ahead) + 5 LDS.128 (W,
// coalesced 512B) + 40 FFMA2 -> FMA/crossbar balanced at 1600 cyc/step.
// Full-warp bfly k-reduction; fence-free release/acquire per-CTA flag barrier.
// ============================================================================
extern __shared__ float smem_dyn[];
__global__ __launch_bounds__(256,1)
void recur_kernel(const float* __restrict__ W_h, const float* __restrict__ xpre,
                  const float* __restrict__ sz,
                  bf16* __restrict__ ot_hi, bf16* __restrict__ ot_lo,
                  float* __restrict__ dout_h){
    float* Wsh = smem_dyn;               // [40][1280]
    float* red = smem_dyn + EPC*DD;      // [8 warps][20]
    const int tid = threadIdx.x;
    const int g   = blockIdx.x >> 5;     // group
    const int c   = blockIdx.x & 31;     // CTA in group
    const int e0  = c*EPC;
    const int b0  = g*GB;

    {   // load W_h slice (rows e0..e0+39 contiguous)
        const float4* Wsrc = (const float4*)(W_h + (size_t)e0*DD);
        float4* Wdst = (float4*)Wsh;
        for (int idx = tid; idx < EPC*DD/4; idx += 256) Wdst[idx] = Wsrc[idx];
    }
    __syncthreads();

    const int w = tid >> 5, l = tid & 31;

    // epilogue mapping: tid<160 -> (bl, eg)
    const int bl = tid / EPC;             // 0..3
    const int eg = tid - bl*EPC;          // 0..39
    const bool epi = (tid < 160);
    const int rw = eg / 5, re5 = eg - rw*5;

    const float* wrow = Wsh + (size_t)(w*5)*DD + (l << 2);

    for (int t=0; t<TT; t++){
        // prefetch epilogue operands (latency hidden behind compute)
        float xp = 0.f, zz = 0.f;
        if (epi){
            xp = xpre[(size_t)(t*BB + b0 + bl)*DD + e0 + eg];
            zz = sz[(size_t)(b0 + bl)*TT*DD + (size_t)t*DD + e0 + eg];
        }

        const float* hb = g_h[t&1] + (size_t)b0*DD + (l << 2);
        float4 hc0 = __ldcg((const float4*)(hb));
        float4 hc1 = __ldcg((const float4*)(hb + DD));
        float4 hc2 = __ldcg((const float4*)(hb + 2*DD));
        float4 hc3 = __ldcg((const float4*)(hb + 3*DD));

        ull acc[4][5];
        #pragma unroll
        for (int b=0;b<4;b++)
            #pragma unroll
            for (int e=0;e<5;e++) acc[b][e]=0ULL;

        #pragma unroll
        for (int it=0; it<10; it++){
            float4 hn0, hn1, hn2, hn3;
            if (it < 9){
                const float* hb2 = hb + (it+1)*128;
                hn0 = __ldcg((const float4*)(hb2));
                hn1 = __ldcg((const float4*)(hb2 + DD));
                hn2 = __ldcg((const float4*)(hb2 + 2*DD));
                hn3 = __ldcg((const float4*)(hb2 + 3*DD));
            }
            ull p0 = pkxy(hc0.x,hc0.y), q0 = pkxy(hc0.z,hc0.w);
            ull p1 = pkxy(hc1.x,hc1.y), q1 = pkxy(hc1.z,hc1.w);
            ull p2 = pkxy(hc2.x,hc2.y), q2 = pkxy(hc2.z,hc2.w);
            ull p3 = pkxy(hc3.x,hc3.y), q3 = pkxy(hc3.z,hc3.w);
            const float* wp = wrow + it*128;
            #pragma unroll
            for (int e=0;e<5;e++){
                ulonglong2 wv = *(const ulonglong2*)(wp + (size_t)e*DD);
                acc[0][e] = ffma2(p0, wv.x, acc[0][e]);
                acc[0][e] = ffma2(q0, wv.y, acc[0][e]);
                acc[1][e] = ffma2(p1, wv.x, acc[1][e]);
                acc[1][e] = ffma2(q1, wv.y, acc[1][e]);
                acc[2][e] = ffma2(p2, wv.x, acc[2][e]);
                acc[2][e] = ffma2(q2, wv.y, acc[2][e]);
                acc[3][e] = ffma2(p3, wv.x, acc[3][e]);
                acc[3][e] = ffma2(q3, wv.y, acc[3][e]);
            }
            hc0=hn0; hc1=hn1; hc2=hn2; hc3=hn3;
        }

        // reduce over 32 lanes (k-split)
        float s[4][5];
        #pragma unroll
        for (int b=0;b<4;b++)
            #pragma unroll
            for (int e=0;e<5;e++) s[b][e] = hadd(acc[b][e]);
        #pragma unroll
        for (int d=1; d<32; d<<=1){
            #pragma unroll
            for (int b=0;b<4;b++)
                #pragma unroll
                for (int e=0;e<5;e++)
                    s[b][e] += __shfl_xor_sync(0xffffffffu, s[b][e], d);
        }
        if (l == 0){
            float* rp = red + w*20;
            #pragma unroll
            for (int b=0;b<4;b++)
                #pragma unroll
                for (int e=0;e<5;e++) rp[b*5+e] = s[b][e];
        }
        __syncthreads();

        if (epi){
            float ssum = red[rw*20 + bl*5 + re5];
            float h = tanh_fast(xp + ssum);
            __stcg(&g_h[(t+1)&1][(size_t)(b0 + bl)*DD + e0 + eg], h);
            float op = h * zz;
            size_t oidx = (size_t)(t*BB + b0 + bl)*DD + e0 + eg;
            bf16 hi, lo; hilo(op, hi, lo);
            ot_hi[oidx] = hi;
            ot_lo[oidx] = lo;
            if (dout_h != nullptr && t == TT-1) dout_h[(size_t)(b0 + bl)*DD + e0 + eg] = h;
        }
        __syncthreads();                       // all stores of this CTA done

        if (tid == 0) st_release_u32(&g_flagv[g][c][0], (uint32_t)(t+1));
        if (tid < 32){
            const uint32_t* fp = &g_flagv[g][tid][0];
            const uint32_t target = (uint32_t)(t+1);
            long long guard = 0;
            while (true){
                uint32_t v = ld_acquire_u32(fp);
                if (__all_sync(0xffffffffu, v >= target)) break;
                if (++guard > 8000000LL) break;   // anti-hang bailout
                __nanosleep(20);
            }
        }
        __syncthreads();
    }
}

// ============================================================================
extern "C" void kernel_launch(void* const* d_in, const int* in_sizes, int n_in,
                              void* d_out, int out_size){
    const float* x     = (const float*)d_in[0];
    const float* W_in  = (const float*)d_in[1];
    const float* W_out = (const float*)d_in[2];
    const float* W_x   = (const float*)d_in[3];
    const float* W_h   = (const float*)d_in[4];
    const float* bias  = (const float*)d_in[5];
    float* out = (float*)d_out;

    const int recur_smem = (EPC*DD + 8*20 + 32) * 4;       // ~205.6 KB
    cudaFuncSetAttribute(recur_kernel, cudaFuncAttributeMaxDynamicSharedMemorySize, recur_smem);

    float* dout_h = (out_size >= BT*DD + BB*DD) ? (out + (size_t)BT*DD) : nullptr;

    float *sz_p, *xpre_p;
    bf16 *xt_hi, *xt_lo, *pt_hi, *pt_lo, *ot_hi, *ot_lo;
    bf16 *wi_hi, *wi_lo, *wx_hi, *wx_lo, *wo_hi, *wo_lo;
    cudaGetSymbolAddress((void**)&sz_p,   g_sz);
    cudaGetSymbolAddress((void**)&xpre_p, g_xpre);
    cudaGetSymbolAddress((void**)&xt_hi,  g_xt_hi);
    cudaGetSymbolAddress((void**)&xt_lo,  g_xt_lo);
    cudaGetSymbolAddress((void**)&pt_hi,  g_pt_hi);
    cudaGetSymbolAddress((void**)&pt_lo,  g_pt_lo);
    cudaGetSymbolAddress((void**)&ot_hi,  g_ot_hi);
    cudaGetSymbolAddress((void**)&ot_lo,  g_ot_lo);
    cudaGetSymbolAddress((void**)&wi_hi,  g_wi_hi);
    cudaGetSymbolAddress((void**)&wi_lo,  g_wi_lo);
    cudaGetSymbolAddress((void**)&wx_hi,  g_wx_hi);
    cudaGetSymbolAddress((void**)&wx_lo,  g_wx_lo);
    cudaGetSymbolAddress((void**)&wo_hi,  g_wo_hi);
    cudaGetSymbolAddress((void**)&wo_lo,  g_wo_lo);

    reset_kernel<<<80, 256>>>();

    convert_hilo<<<(BT*DD/4 + 255)/256, 256>>>(x,     xt_hi, xt_lo, BT*DD/4);
    convert_hilo<<<(2*DD*DD/4 + 255)/256, 256>>>(W_in,  wi_hi, wi_lo, 2*DD*DD/4);
    convert_hilo<<<(DD*DD/4 + 255)/256, 256>>>(W_x,   wx_hi, wx_lo, DD*DD/4);
    convert_hilo<<<(DD*DD/4 + 255)/256, 256>>>(W_out, wo_hi, wo_lo, DD*DD/4);

    gemm_mma<0><<<dim3(BT/128, (2*DD)/128), 256>>>(xt_hi, xt_lo, wi_hi, wi_lo,
                                                   nullptr, sz_p, pt_hi, pt_lo);

    gemm_mma<1><<<dim3(BT/128, DD/128), 256>>>(pt_hi, pt_lo, wx_hi, wx_lo,
                                               bias, xpre_p, nullptr, nullptr);

    recur_kernel<<<NGRP*GCTAS, 256, recur_smem>>>(W_h, xpre_p, sz_p, ot_hi, ot_lo, dout_h);

    gemm_mma<2><<<dim3(BT/128, DD/128), 256>>>(ot_hi, ot_lo, wo_hi, wo_lo,
                                               nullptr, out, nullptr, nullptr);
}

// round 8
// speedup vs baseline: 1.5646x; 1.0475x over previous
#include <cuda_runtime.h>
#include <cuda_bf16.h>
#include <math.h>
#include <stdint.h>

typedef unsigned long long ull;
typedef __nv_bfloat16 bf16;

#define BB 16
#define TT 2048
#define DD 1280
#define BT (BB*TT)          // 32768
#define ASTR 40             // gemm smem row stride (bf16)

#define NGRP 4              // independent recurrence groups
#define GCTAS 32            // CTAs per group
#define GB 4                // batches per group
#define EPC 40              // e-rows of W_h per CTA
#define RTHREADS 512

// ---------------- scratch (static __device__) ----------------
__device__ float g_sz[BT*DD];        // silu(z), fp32, rows b*T+t
__device__ float g_xpre[BT*DD];      // x_pre,   fp32, rows t*B+b
__device__ float g_h[2][BB*DD];
__device__ uint32_t g_flagv[NGRP][GCTAS][32];   // per-CTA release flags (128B apart)

// bf16 hi/lo row-major operands
__device__ bf16 g_xt_hi[BT*DD],  g_xt_lo[BT*DD];     // x
__device__ bf16 g_pt_hi[BT*DD],  g_pt_lo[BT*DD];     // silu(xproj)
__device__ bf16 g_ot_hi[BT*DD],  g_ot_lo[BT*DD];     // h*silu(z), rows t*B+b
__device__ bf16 g_wi_hi[2*DD*DD], g_wi_lo[2*DD*DD];  // W_in
__device__ bf16 g_wx_hi[DD*DD],   g_wx_lo[DD*DD];    // W_x
__device__ bf16 g_wo_hi[DD*DD],   g_wo_lo[DD*DD];    // W_out

// ---------------- helpers ----------------
__device__ __forceinline__ ull ffma2(ull a, ull b, ull c){
    ull d; asm("fma.rn.f32x2 %0, %1, %2, %3;" : "=l"(d) : "l"(a), "l"(b), "l"(c)); return d;
}
__device__ __forceinline__ float2 unpk(ull v){
    float2 r; asm("mov.b64 {%0, %1}, %2;" : "=f"(r.x), "=f"(r.y) : "l"(v)); return r;
}
__device__ __forceinline__ float hadd(ull v){ float2 f = unpk(v); return f.x + f.y; }
__device__ __forceinline__ float silu_f(float v){ return v * (1.f/(1.f + __expf(-v))); }
__device__ __forceinline__ float tanh_fast(float x){
    float c = fminf(fmaxf(x, -12.f), 12.f);
    float e = __expf(2.f*c);
    return __fdividef(e - 1.f, e + 1.f);
}
__device__ __forceinline__ uint32_t smem_u32(const void* p){
    uint32_t a; asm("{ .reg .u64 t; cvta.to.shared.u64 t, %1; cvt.u32.u64 %0, t; }" : "=r"(a) : "l"(p));
    return a;
}
__device__ __forceinline__ void st_release_u32(uint32_t* p, uint32_t v){
    asm volatile("st.release.gpu.global.u32 [%0], %1;" :: "l"(p), "r"(v) : "memory");
}
__device__ __forceinline__ uint32_t ld_acquire_u32(const uint32_t* p){
    uint32_t v;
    asm volatile("ld.acquire.gpu.global.u32 %0, [%1];" : "=r"(v) : "l"(p) : "memory");
    return v;
}
__device__ __forceinline__ ulonglong2 ldcg_u2(const void* p){
    ulonglong2 v;
    asm volatile("ld.global.cg.v2.u64 {%0, %1}, [%2];" : "=l"(v.x), "=l"(v.y) : "l"(p));
    return v;
}
__device__ __forceinline__ void cpa16(uint32_t s, const void* g){
    asm volatile("cp.async.cg.shared.global [%0], [%1], 16;" :: "r"(s), "l"(g));
}
__device__ __forceinline__ void cpa_commit(){ asm volatile("cp.async.commit_group;"); }
__device__ __forceinline__ void cpa_wait1(){ asm volatile("cp.async.wait_group 1;"); }

__device__ __forceinline__ void ldsm4(uint32_t* r, uint32_t addr){
    asm volatile("ldmatrix.sync.aligned.m8n8.x4.shared.b16 {%0,%1,%2,%3}, [%4];"
        : "=r"(r[0]), "=r"(r[1]), "=r"(r[2]), "=r"(r[3]) : "r"(addr));
}
__device__ __forceinline__ void mma16816(float* c, const uint32_t* a, uint32_t b0, uint32_t b1){
    asm volatile("mma.sync.aligned.m16n8k16.row.col.f32.bf16.bf16.f32 "
        "{%0,%1,%2,%3}, {%4,%5,%6,%7}, {%8,%9}, {%0,%1,%2,%3};"
        : "+f"(c[0]), "+f"(c[1]), "+f"(c[2]), "+f"(c[3])
        : "r"(a[0]), "r"(a[1]), "r"(a[2]), "r"(a[3]), "r"(b0), "r"(b1));
}
__device__ __forceinline__ void hilo(float v, bf16& h, bf16& l){
    h = __float2bfloat16(v);
    l = __float2bfloat16(v - __bfloat162float(h));
}

// ---------------- reset ----------------
__global__ void reset_kernel(){
    int i = blockIdx.x*blockDim.x + threadIdx.x;
    if (i < NGRP*GCTAS*32) ((uint32_t*)g_flagv)[i] = 0u;
    if (i < BB*DD) g_h[0][i] = 0.f;
}

// ---------------- fp32 -> bf16 hi/lo ----------------
__global__ void convert_hilo(const float* __restrict__ src, bf16* __restrict__ hi,
                             bf16* __restrict__ lo, int n4){
    int i = blockIdx.x*blockDim.x + threadIdx.x;
    if (i >= n4) return;
    float4 v = *(const float4*)(src + (size_t)i*4);
    bf16 h0,l0,h1,l1,h2,l2,h3,l3;
    hilo(v.x,h0,l0); hilo(v.y,h1,l1); hilo(v.z,h2,l2); hilo(v.w,h3,l3);
    __nv_bfloat162 hh0; hh0.x=h0; hh0.y=h1;
    __nv_bfloat162 hh1; hh1.x=h2; hh1.y=h3;
    __nv_bfloat162 ll0; ll0.x=l0; ll0.y=l1;
    __nv_bfloat162 ll1; ll1.x=l2; ll1.y=l3;
    *(__nv_bfloat162*)(hi + (size_t)i*4)     = hh0;
    *(__nv_bfloat162*)(hi + (size_t)i*4 + 2) = hh1;
    *(__nv_bfloat162*)(lo + (size_t)i*4)     = ll0;
    *(__nv_bfloat162*)(lo + (size_t)i*4 + 2) = ll1;
}

// ============================================================================
// bf16 mma.sync GEMM with 3-term hi/lo split (R5-verified, unchanged).
// ============================================================================
template<int MODE>
__global__ __launch_bounds__(256,2)
void gemm_mma(const bf16* __restrict__ Ahi, const bf16* __restrict__ Alo,
              const bf16* __restrict__ Bhi, const bf16* __restrict__ Blo,
              const float* __restrict__ bias, float* __restrict__ fout,
              bf16* __restrict__ thi, bf16* __restrict__ tlo){
    __shared__ __align__(16) bf16 sA[2][128*ASTR];
    __shared__ __align__(16) bf16 sB[2][128*ASTR];

    const int tid = threadIdx.x, wid = tid >> 5, l = tid & 31;
    const int m0 = blockIdx.x*128, n0 = blockIdx.y*128;
    const int wm = wid >> 2, wn = wid & 3;

    const uint32_t aB = smem_u32(sA), bB = smem_u32(sB);

    const bf16* Asegs[3] = {Ahi, Alo, Ahi};
    const bf16* Bsegs[3] = {Bhi, Bhi, Blo};

    const int lrow0 = tid >> 2;
    const int lcol  = (tid & 3) << 3;
    const int NIT = 3*(DD/32);

    auto load_tile = [&](int it, int st){
        int seg = it / (DD/32);
        int kt  = (it % (DD/32)) * 32;
        const bf16* As = Asegs[seg];
        const bf16* Bs = Bsegs[seg];
        uint32_t sa = aB + st*10240u, sb = bB + st*10240u;
        #pragma unroll
        for (int i=0;i<2;i++){
            int row = lrow0 + i*64;
            cpa16(sa + (uint32_t)(row*ASTR + lcol)*2u, As + (size_t)(m0+row)*DD + kt + lcol);
            cpa16(sb + (uint32_t)(row*ASTR + lcol)*2u, Bs + (size_t)(n0+row)*DD + kt + lcol);
        }
    };

    float acc[4][4][4];
    #pragma unroll
    for (int i=0;i<4;i++)
        #pragma unroll
        for (int j=0;j<4;j++)
            #pragma unroll
            for (int k=0;k<4;k++) acc[i][j][k]=0.f;

    const uint32_t aLane = (uint32_t)(((l & 15)*ASTR + ((l >> 4) << 3)) * 2);
    const uint32_t bLane = (uint32_t)((((l & 7) + ((l >> 4) << 3))*ASTR + (((l >> 3) & 1) << 3)) * 2);

    load_tile(0, 0);
    cpa_commit();

    for (int it=0; it<NIT; it++){
        int st = it & 1;
        if (it + 1 < NIT) load_tile(it+1, (it+1)&1);
        cpa_commit();
        cpa_wait1();
        __syncthreads();

        uint32_t saw = aB + st*10240u + (uint32_t)(wm*64*ASTR)*2u + aLane;
        uint32_t sbw = bB + st*10240u + (uint32_t)(wn*32*ASTR)*2u + bLane;
        #pragma unroll
        for (int k16=0; k16<2; k16++){
            uint32_t a[4][4], b[2][4];
            #pragma unroll
            for (int mi=0;mi<4;mi++)
                ldsm4(a[mi], saw + (uint32_t)(mi*16*ASTR)*2u + k16*32u);
            #pragma unroll
            for (int nj=0;nj<2;nj++)
                ldsm4(b[nj], sbw + (uint32_t)(nj*16*ASTR)*2u + k16*32u);
            #pragma unroll
            for (int mi=0;mi<4;mi++){
                #pragma unroll
                for (int ni=0;ni<4;ni++){
                    int nj = ni >> 1, half = ni & 1;
                    mma16816(acc[mi][ni], a[mi], b[nj][half*2], b[nj][half*2+1]);
                }
            }
        }
        __syncthreads();
    }

    const int mwarp = m0 + wm*64, nwarp = n0 + wn*32;
    const int rl = l >> 2, cl = (l & 3) << 1;
    #pragma unroll
    for (int mi=0;mi<4;mi++){
        #pragma unroll
        for (int ni=0;ni<4;ni++){
            const float* c = acc[mi][ni];
            int col = nwarp + ni*8 + cl;
            #pragma unroll
            for (int h=0; h<2; h++){
                int m = mwarp + mi*16 + rl + h*8;
                float v0 = c[h*2], v1 = c[h*2+1];
                if (MODE == 0){
                    if (col < DD){
                        float s0 = silu_f(v0), s1 = silu_f(v1);
                        bf16 h0,l0,h1,l1; hilo(s0,h0,l0); hilo(s1,h1,l1);
                        __nv_bfloat162 hh; hh.x=h0; hh.y=h1;
                        __nv_bfloat162 ll; ll.x=l0; ll.y=l1;
                        *(__nv_bfloat162*)(thi + (size_t)m*DD + col) = hh;
                        *(__nv_bfloat162*)(tlo + (size_t)m*DD + col) = ll;
                    } else {
                        float2 o; o.x = silu_f(v0); o.y = silu_f(v1);
                        *(float2*)(fout + (size_t)m*DD + (col - DD)) = o;
                    }
                } else if (MODE == 1){
                    float2 o; o.x = v0 + __ldg(bias + col); o.y = v1 + __ldg(bias + col + 1);
                    int ro = ((m & (TT-1)) << 4) | (m >> 11);
                    *(float2*)(fout + (size_t)ro*DD + col) = o;
                } else {
                    int bb = m & 15, tt = m >> 4;
                    float2 o; o.x = v0; o.y = v1;
                    *(float2*)(fout + (size_t)bb*TT*DD + (size_t)tt*DD + col) = o;
                }
            }
        }
    }
}

// ============================================================================
// Recurrence v4: 4 groups x 32 CTAs, 512 threads (16 warps, occ 25%).
// Warp w: e-group eg=w>>1 (5 e-rows), k-half kh=w&1 (640 k). Lane l: k-quad
// l*4 within 128-float iter window; 5 iters. h loaded as ulonglong2 (raw
// packed f32x2 pairs -> zero pack MOVs). 3-stage shfl + smem combine of 8
// k-partials. Fence-free release/acquire barrier, spin-first polling.
// ============================================================================
extern __shared__ float smem_dyn[];
__global__ __launch_bounds__(RTHREADS,1)
void recur_kernel(const float* __restrict__ W_h, const float* __restrict__ xpre,
                  const float* __restrict__ sz,
                  bf16* __restrict__ ot_hi, bf16* __restrict__ ot_lo,
                  float* __restrict__ dout_h){
    float* Wsh = smem_dyn;               // [40][1280]
    float* red = smem_dyn + EPC*DD;      // [8 eg][8 part][20]
    const int tid = threadIdx.x;
    const int g   = blockIdx.x >> 5;
    const int c   = blockIdx.x & 31;
    const int e0  = c*EPC;
    const int b0  = g*GB;

    {   // load W_h slice (rows e0..e0+39 contiguous)
        const float4* Wsrc = (const float4*)(W_h + (size_t)e0*DD);
        float4* Wdst = (float4*)Wsh;
        for (int idx = tid; idx < EPC*DD/4; idx += RTHREADS) Wdst[idx] = Wsrc[idx];
    }
    __syncthreads();

    const int w  = tid >> 5, l = tid & 31;
    const int eg = w >> 1;                // 0..7
    const int kh = w & 1;                 // k-half
    const int part = kh*4 + (l >> 3);     // k-partial index 0..7 (for lanes l%8==0)

    // epilogue mapping: tid<160 -> (bl, eg2, re)
    const int bl = tid / EPC;             // 0..3
    const int el = tid - bl*EPC;          // 0..39
    const bool epi = (tid < 160);
    const int eg2 = el / 5, re5 = el - eg2*5;

    const float* wrow = Wsh + (size_t)(eg*5)*DD + kh*640 + (l << 2);

    for (int t=0; t<TT; t++){
        // prefetch epilogue operands
        float xp = 0.f, zz = 0.f;
        if (epi){
            xp = xpre[(size_t)(t*BB + b0 + bl)*DD + e0 + el];
            zz = sz[(size_t)(b0 + bl)*TT*DD + (size_t)t*DD + e0 + el];
        }

        const float* hb = g_h[t&1] + (size_t)b0*DD + kh*640 + (l << 2);
        ulonglong2 hc0 = ldcg_u2(hb);
        ulonglong2 hc1 = ldcg_u2(hb + DD);
        ulonglong2 hc2 = ldcg_u2(hb + 2*DD);
        ulonglong2 hc3 = ldcg_u2(hb + 3*DD);

        ull acc[4][5];
        #pragma unroll
        for (int b=0;b<4;b++)
            #pragma unroll
            for (int e=0;e<5;e++) acc[b][e]=0ULL;

        #pragma unroll
        for (int it=0; it<5; it++){
            ulonglong2 hn0, hn1, hn2, hn3;
            if (it < 4){
                const float* hb2 = hb + (it+1)*128;
                hn0 = ldcg_u2(hb2);
                hn1 = ldcg_u2(hb2 + DD);
                hn2 = ldcg_u2(hb2 + 2*DD);
                hn3 = ldcg_u2(hb2 + 3*DD);
            }
            const float* wp = wrow + it*128;
            #pragma unroll
            for (int e=0;e<5;e++){
                ulonglong2 wv = *(const ulonglong2*)(wp + (size_t)e*DD);
                acc[0][e] = ffma2(hc0.x, wv.x, acc[0][e]);
                acc[0][e] = ffma2(hc0.y, wv.y, acc[0][e]);
                acc[1][e] = ffma2(hc1.x, wv.x, acc[1][e]);
                acc[1][e] = ffma2(hc1.y, wv.y, acc[1][e]);
                acc[2][e] = ffma2(hc2.x, wv.x, acc[2][e]);
                acc[2][e] = ffma2(hc2.y, wv.y, acc[2][e]);
                acc[3][e] = ffma2(hc3.x, wv.x, acc[3][e]);
                acc[3][e] = ffma2(hc3.y, wv.y, acc[3][e]);
            }
            hc0=hn0; hc1=hn1; hc2=hn2; hc3=hn3;
        }

        // 3-stage lane reduction (within 8-lane k-octet groups)
        float s[4][5];
        #pragma unroll
        for (int b=0;b<4;b++)
            #pragma unroll
            for (int e=0;e<5;e++) s[b][e] = hadd(acc[b][e]);
        #pragma unroll
        for (int d=1; d<8; d<<=1){
            #pragma unroll
            for (int b=0;b<4;b++)
                #pragma unroll
                for (int e=0;e<5;e++)
                    s[b][e] += __shfl_xor_sync(0xffffffffu, s[b][e], d);
        }
        if ((l & 7) == 0){
            float* rp = red + (eg*8 + part)*20;
            #pragma unroll
            for (int b=0;b<4;b++)
                #pragma unroll
                for (int e=0;e<5;e++) rp[b*5+e] = s[b][e];
        }
        __syncthreads();

        if (epi){
            const float* rp = red + eg2*160 + bl*5 + re5;
            float ssum = 0.f;
            #pragma unroll
            for (int p=0;p<8;p++) ssum += rp[p*20];
            float h = tanh_fast(xp + ssum);
            __stcg(&g_h[(t+1)&1][(size_t)(b0 + bl)*DD + e0 + el], h);
            float op = h * zz;
            size_t oidx = (size_t)(t*BB + b0 + bl)*DD + e0 + el;
            bf16 hi, lo; hilo(op, hi, lo);
            ot_hi[oidx] = hi;
            ot_lo[oidx] = lo;
            if (dout_h != nullptr && t == TT-1) dout_h[(size_t)(b0 + bl)*DD + e0 + el] = h;
        }
        __syncthreads();                       // all h stores of this CTA done

        if (tid == 0) st_release_u32(&g_flagv[g][c][0], (uint32_t)(t+1));
        if (tid < 32){
            const uint32_t* fp = &g_flagv[g][tid][0];
            const uint32_t target = (uint32_t)(t+1);
            long long guard = 0;
            while (true){
                uint32_t v = ld_acquire_u32(fp);
                if (__all_sync(0xffffffffu, v >= target)) break;
                ++guard;
                if (guard > 64) __nanosleep(40);
                if (guard > 8000000LL) break;   // anti-hang bailout
            }
        }
        __syncthreads();
    }
}

// ============================================================================
extern "C" void kernel_launch(void* const* d_in, const int* in_sizes, int n_in,
                              void* d_out, int out_size){
    const float* x     = (const float*)d_in[0];
    const float* W_in  = (const float*)d_in[1];
    const float* W_out = (const float*)d_in[2];
    const float* W_x   = (const float*)d_in[3];
    const float* W_h   = (const float*)d_in[4];
    const float* bias  = (const float*)d_in[5];
    float* out = (float*)d_out;

    const int recur_smem = (EPC*DD + 8*8*20 + 32) * 4;     // ~210 KB
    cudaFuncSetAttribute(recur_kernel, cudaFuncAttributeMaxDynamicSharedMemorySize, recur_smem);

    float* dout_h = (out_size >= BT*DD + BB*DD) ? (out + (size_t)BT*DD) : nullptr;

    float *sz_p, *xpre_p;
    bf16 *xt_hi, *xt_lo, *pt_hi, *pt_lo, *ot_hi, *ot_lo;
    bf16 *wi_hi, *wi_lo, *wx_hi, *wx_lo, *wo_hi, *wo_lo;
    cudaGetSymbolAddress((void**)&sz_p,   g_sz);
    cudaGetSymbolAddress((void**)&xpre_p, g_xpre);
    cudaGetSymbolAddress((void**)&xt_hi,  g_xt_hi);
    cudaGetSymbolAddress((void**)&xt_lo,  g_xt_lo);
    cudaGetSymbolAddress((void**)&pt_hi,  g_pt_hi);
    cudaGetSymbolAddress((void**)&pt_lo,  g_pt_lo);
    cudaGetSymbolAddress((void**)&ot_hi,  g_ot_hi);
    cudaGetSymbolAddress((void**)&ot_lo,  g_ot_lo);
    cudaGetSymbolAddress((void**)&wi_hi,  g_wi_hi);
    cudaGetSymbolAddress((void**)&wi_lo,  g_wi_lo);
    cudaGetSymbolAddress((void**)&wx_hi,  g_wx_hi);
    cudaGetSymbolAddress((void**)&wx_lo,  g_wx_lo);
    cudaGetSymbolAddress((void**)&wo_hi,  g_wo_hi);
    cudaGetSymbolAddress((void**)&wo_lo,  g_wo_lo);

    reset_kernel<<<80, 256>>>();

    convert_hilo<<<(BT*DD/4 + 255)/256, 256>>>(x,     xt_hi, xt_lo, BT*DD/4);
    convert_hilo<<<(2*DD*DD/4 + 255)/256, 256>>>(W_in,  wi_hi, wi_lo, 2*DD*DD/4);
    convert_hilo<<<(DD*DD/4 + 255)/256, 256>>>(W_x,   wx_hi, wx_lo, DD*DD/4);
    convert_hilo<<<(DD*DD/4 + 255)/256, 256>>>(W_out, wo_hi, wo_lo, DD*DD/4);

    gemm_mma<0><<<dim3(BT/128, (2*DD)/128), 256>>>(xt_hi, xt_lo, wi_hi, wi_lo,
                                                   nullptr, sz_p, pt_hi, pt_lo);

    gemm_mma<1><<<dim3(BT/128, DD/128), 256>>>(pt_hi, pt_lo, wx_hi, wx_lo,
                                               bias, xpre_p, nullptr, nullptr);

    recur_kernel<<<NGRP*GCTAS, RTHREADS, recur_smem>>>(W_h, xpre_p, sz_p, ot_hi, ot_lo, dout_h);

    gemm_mma<2><<<dim3(BT/128, DD/128), 256>>>(ot_hi, ot_lo, wo_hi, wo_lo,
                                               nullptr, out, nullptr, nullptr);
}

// round 9
// speedup vs baseline: 1.6039x; 1.0251x over previous
#include <cuda_runtime.h>
#include <cuda_bf16.h>
#include <math.h>
#include <stdint.h>

typedef unsigned long long ull;
typedef __nv_bfloat16 bf16;

#define BB 16
#define TT 2048
#define DD 1280
#define BT (BB*TT)          // 32768
#define ASTR 40             // gemm smem row stride (bf16)

#define NGRP 4              // independent recurrence groups
#define GCTAS 32            // CTAs per group
#define GB 4                // batches per group
#define EPC 40              // e-rows of W_h per CTA
#define RTHREADS 512

// ---------------- scratch (static __device__) ----------------
__device__ float g_sz[BT*DD];        // silu(z), fp32, rows b*T+t
__device__ float g_xpre[BT*DD];      // x_pre,   fp32, rows t*B+b
__device__ float g_h[2][BB*DD];
__device__ uint32_t g_flagv[NGRP][GCTAS][32];   // per-CTA release flags (128B apart)

// bf16 hi/lo row-major operands
__device__ bf16 g_xt_hi[BT*DD],  g_xt_lo[BT*DD];     // x
__device__ bf16 g_pt_hi[BT*DD],  g_pt_lo[BT*DD];     // silu(xproj)
__device__ bf16 g_ot_hi[BT*DD],  g_ot_lo[BT*DD];     // h*silu(z), rows t*B+b
__device__ bf16 g_wi_hi[2*DD*DD], g_wi_lo[2*DD*DD];  // W_in
__device__ bf16 g_wx_hi[DD*DD],   g_wx_lo[DD*DD];    // W_x
__device__ bf16 g_wo_hi[DD*DD],   g_wo_lo[DD*DD];    // W_out

// ---------------- helpers ----------------
__device__ __forceinline__ ull ffma2(ull a, ull b, ull c){
    ull d; asm("fma.rn.f32x2 %0, %1, %2, %3;" : "=l"(d) : "l"(a), "l"(b), "l"(c)); return d;
}
__device__ __forceinline__ float2 unpk(ull v){
    float2 r; asm("mov.b64 {%0, %1}, %2;" : "=f"(r.x), "=f"(r.y) : "l"(v)); return r;
}
__device__ __forceinline__ float hadd(ull v){ float2 f = unpk(v); return f.x + f.y; }
__device__ __forceinline__ float silu_f(float v){ return v * (1.f/(1.f + __expf(-v))); }
__device__ __forceinline__ float tanh_fast(float x){
    float c = fminf(fmaxf(x, -12.f), 12.f);
    float e = __expf(2.f*c);
    return __fdividef(e - 1.f, e + 1.f);
}
__device__ __forceinline__ uint32_t smem_u32(const void* p){
    uint32_t a; asm("{ .reg .u64 t; cvta.to.shared.u64 t, %1; cvt.u32.u64 %0, t; }" : "=r"(a) : "l"(p));
    return a;
}
__device__ __forceinline__ void st_release_u32(uint32_t* p, uint32_t v){
    asm volatile("st.release.gpu.global.u32 [%0], %1;" :: "l"(p), "r"(v) : "memory");
}
__device__ __forceinline__ uint32_t ld_acquire_u32(const uint32_t* p){
    uint32_t v;
    asm volatile("ld.acquire.gpu.global.u32 %0, [%1];" : "=r"(v) : "l"(p) : "memory");
    return v;
}
__device__ __forceinline__ ulonglong2 ldcg_u2(const void* p){
    ulonglong2 v;
    asm volatile("ld.global.cg.v2.u64 {%0, %1}, [%2];" : "=l"(v.x), "=l"(v.y) : "l"(p));
    return v;
}
__device__ __forceinline__ void cpa16(uint32_t s, const void* g){
    asm volatile("cp.async.cg.shared.global [%0], [%1], 16;" :: "r"(s), "l"(g));
}
__device__ __forceinline__ void cpa_commit(){ asm volatile("cp.async.commit_group;"); }
__device__ __forceinline__ void cpa_wait1(){ asm volatile("cp.async.wait_group 1;"); }

__device__ __forceinline__ void ldsm4(uint32_t* r, uint32_t addr){
    asm volatile("ldmatrix.sync.aligned.m8n8.x4.shared.b16 {%0,%1,%2,%3}, [%4];"
        : "=r"(r[0]), "=r"(r[1]), "=r"(r[2]), "=r"(r[3]) : "r"(addr));
}
__device__ __forceinline__ void mma16816(float* c, const uint32_t* a, uint32_t b0, uint32_t b1){
    asm volatile("mma.sync.aligned.m16n8k16.row.col.f32.bf16.bf16.f32 "
        "{%0,%1,%2,%3}, {%4,%5,%6,%7}, {%8,%9}, {%0,%1,%2,%3};"
        : "+f"(c[0]), "+f"(c[1]), "+f"(c[2]), "+f"(c[3])
        : "r"(a[0]), "r"(a[1]), "r"(a[2]), "r"(a[3]), "r"(b0), "r"(b1));
}
__device__ __forceinline__ void hilo(float v, bf16& h, bf16& l){
    h = __float2bfloat16(v);
    l = __float2bfloat16(v - __bfloat162float(h));
}

// ---------------- reset ----------------
__global__ void reset_kernel(){
    int i = blockIdx.x*blockDim.x + threadIdx.x;
    if (i < NGRP*GCTAS*32) ((uint32_t*)g_flagv)[i] = 0u;
    if (i < BB*DD) g_h[0][i] = 0.f;
}

// ---------------- fp32 -> bf16 hi/lo ----------------
__global__ void convert_hilo(const float* __restrict__ src, bf16* __restrict__ hi,
                             bf16* __restrict__ lo, int n4){
    int i = blockIdx.x*blockDim.x + threadIdx.x;
    if (i >= n4) return;
    float4 v = *(const float4*)(src + (size_t)i*4);
    bf16 h0,l0,h1,l1,h2,l2,h3,l3;
    hilo(v.x,h0,l0); hilo(v.y,h1,l1); hilo(v.z,h2,l2); hilo(v.w,h3,l3);
    __nv_bfloat162 hh0; hh0.x=h0; hh0.y=h1;
    __nv_bfloat162 hh1; hh1.x=h2; hh1.y=h3;
    __nv_bfloat162 ll0; ll0.x=l0; ll0.y=l1;
    __nv_bfloat162 ll1; ll1.x=l2; ll1.y=l3;
    *(__nv_bfloat162*)(hi + (size_t)i*4)     = hh0;
    *(__nv_bfloat162*)(hi + (size_t)i*4 + 2) = hh1;
    *(__nv_bfloat162*)(lo + (size_t)i*4)     = ll0;
    *(__nv_bfloat162*)(lo + (size_t)i*4 + 2) = ll1;
}

// ============================================================================
// bf16 mma.sync GEMM with 3-term hi/lo split (R5-verified, unchanged).
// ============================================================================
template<int MODE>
__global__ __launch_bounds__(256,2)
void gemm_mma(const bf16* __restrict__ Ahi, const bf16* __restrict__ Alo,
              const bf16* __restrict__ Bhi, const bf16* __restrict__ Blo,
              const float* __restrict__ bias, float* __restrict__ fout,
              bf16* __restrict__ thi, bf16* __restrict__ tlo){
    __shared__ __align__(16) bf16 sA[2][128*ASTR];
    __shared__ __align__(16) bf16 sB[2][128*ASTR];

    const int tid = threadIdx.x, wid = tid >> 5, l = tid & 31;
    const int m0 = blockIdx.x*128, n0 = blockIdx.y*128;
    const int wm = wid >> 2, wn = wid & 3;

    const uint32_t aB = smem_u32(sA), bB = smem_u32(sB);

    const bf16* Asegs[3] = {Ahi, Alo, Ahi};
    const bf16* Bsegs[3] = {Bhi, Bhi, Blo};

    const int lrow0 = tid >> 2;
    const int lcol  = (tid & 3) << 3;
    const int NIT = 3*(DD/32);

    auto load_tile = [&](int it, int st){
        int seg = it / (DD/32);
        int kt  = (it % (DD/32)) * 32;
        const bf16* As = Asegs[seg];
        const bf16* Bs = Bsegs[seg];
        uint32_t sa = aB + st*10240u, sb = bB + st*10240u;
        #pragma unroll
        for (int i=0;i<2;i++){
            int row = lrow0 + i*64;
            cpa16(sa + (uint32_t)(row*ASTR + lcol)*2u, As + (size_t)(m0+row)*DD + kt + lcol);
            cpa16(sb + (uint32_t)(row*ASTR + lcol)*2u, Bs + (size_t)(n0+row)*DD + kt + lcol);
        }
    };

    float acc[4][4][4];
    #pragma unroll
    for (int i=0;i<4;i++)
        #pragma unroll
        for (int j=0;j<4;j++)
            #pragma unroll
            for (int k=0;k<4;k++) acc[i][j][k]=0.f;

    const uint32_t aLane = (uint32_t)(((l & 15)*ASTR + ((l >> 4) << 3)) * 2);
    const uint32_t bLane = (uint32_t)((((l & 7) + ((l >> 4) << 3))*ASTR + (((l >> 3) & 1) << 3)) * 2);

    load_tile(0, 0);
    cpa_commit();

    for (int it=0; it<NIT; it++){
        int st = it & 1;
        if (it + 1 < NIT) load_tile(it+1, (it+1)&1);
        cpa_commit();
        cpa_wait1();
        __syncthreads();

        uint32_t saw = aB + st*10240u + (uint32_t)(wm*64*ASTR)*2u + aLane;
        uint32_t sbw = bB + st*10240u + (uint32_t)(wn*32*ASTR)*2u + bLane;
        #pragma unroll
        for (int k16=0; k16<2; k16++){
            uint32_t a[4][4], b[2][4];
            #pragma unroll
            for (int mi=0;mi<4;mi++)
                ldsm4(a[mi], saw + (uint32_t)(mi*16*ASTR)*2u + k16*32u);
            #pragma unroll
            for (int nj=0;nj<2;nj++)
                ldsm4(b[nj], sbw + (uint32_t)(nj*16*ASTR)*2u + k16*32u);
            #pragma unroll
            for (int mi=0;mi<4;mi++){
                #pragma unroll
                for (int ni=0;ni<4;ni++){
                    int nj = ni >> 1, half = ni & 1;
                    mma16816(acc[mi][ni], a[mi], b[nj][half*2], b[nj][half*2+1]);
                }
            }
        }
        __syncthreads();
    }

    const int mwarp = m0 + wm*64, nwarp = n0 + wn*32;
    const int rl = l >> 2, cl = (l & 3) << 1;
    #pragma unroll
    for (int mi=0;mi<4;mi++){
        #pragma unroll
        for (int ni=0;ni<4;ni++){
            const float* c = acc[mi][ni];
            int col = nwarp + ni*8 + cl;
            #pragma unroll
            for (int h=0; h<2; h++){
                int m = mwarp + mi*16 + rl + h*8;
                float v0 = c[h*2], v1 = c[h*2+1];
                if (MODE == 0){
                    if (col < DD){
                        float s0 = silu_f(v0), s1 = silu_f(v1);
                        bf16 h0,l0,h1,l1; hilo(s0,h0,l0); hilo(s1,h1,l1);
                        __nv_bfloat162 hh; hh.x=h0; hh.y=h1;
                        __nv_bfloat162 ll; ll.x=l0; ll.y=l1;
                        *(__nv_bfloat162*)(thi + (size_t)m*DD + col) = hh;
                        *(__nv_bfloat162*)(tlo + (size_t)m*DD + col) = ll;
                    } else {
                        float2 o; o.x = silu_f(v0); o.y = silu_f(v1);
                        *(float2*)(fout + (size_t)m*DD + (col - DD)) = o;
                    }
                } else if (MODE == 1){
                    float2 o; o.x = v0 + __ldg(bias + col); o.y = v1 + __ldg(bias + col + 1);
                    int ro = ((m & (TT-1)) << 4) | (m >> 11);
                    *(float2*)(fout + (size_t)ro*DD + col) = o;
                } else {
                    int bb = m & 15, tt = m >> 4;
                    float2 o; o.x = v0; o.y = v1;
                    *(float2*)(fout + (size_t)bb*TT*DD + (size_t)tt*DD + col) = o;
                }
            }
        }
    }
}

// ============================================================================
// Recurrence v5: 4 groups x 32 CTAs, 512 thr. Warp w: eg=w>>2 (10 e-rows),
// kh=w&3 (320 k). Lanes: half-warp lh=l>>4 picks batch pair (2lh, 2lh+1);
// ll=l&15 picks k-quad. Half-warps read the SAME W addresses -> intra-warp
// LDS broadcast dedup keeps W at 204.8KB/step; h redundancy drops 8x->4x
// (crossbar 2880->2240 cyc/step). 4-stage half-warp shfl + 4-partial smem
// combine. Flag released right after h stores; ot writes off critical path;
// next-step poll at loop top with xpre/sz prefetch already in flight.
// ============================================================================
extern __shared__ float smem_dyn[];
__global__ __launch_bounds__(RTHREADS,1)
void recur_kernel(const float* __restrict__ W_h, const float* __restrict__ xpre,
                  const float* __restrict__ sz,
                  bf16* __restrict__ ot_hi, bf16* __restrict__ ot_lo,
                  float* __restrict__ dout_h){
    float* Wsh = smem_dyn;               // [40][1280]
    float* red = smem_dyn + EPC*DD;      // [4 kh][4 b][40 e]
    const int tid = threadIdx.x;
    const int g   = blockIdx.x >> 5;
    const int c   = blockIdx.x & 31;
    const int e0  = c*EPC;
    const int b0  = g*GB;

    {   // load W_h slice (rows e0..e0+39 contiguous)
        const float4* Wsrc = (const float4*)(W_h + (size_t)e0*DD);
        float4* Wdst = (float4*)Wsh;
        for (int idx = tid; idx < EPC*DD/4; idx += RTHREADS) Wdst[idx] = Wsrc[idx];
    }
    __syncthreads();

    const int w  = tid >> 5, l = tid & 31;
    const int eg = w >> 2;                // 0..3: e-rows eg*10..+10
    const int kh = w & 3;                 // k range kh*320
    const int lh = l >> 4;                // half-warp: batch pair
    const int ll = l & 15;                // k-quad within 64-float window
    const int bA = 2*lh;                  // local batches bA, bA+1

    // epilogue mapping: tid<160 -> (bl, el)
    const int bl = tid / EPC;             // 0..3
    const int el = tid - bl*EPC;          // 0..39
    const bool epi = (tid < 160);

    const float* wbase = Wsh + (size_t)(eg*10)*DD + kh*320 + (ll << 2);

    for (int t=0; t<TT; t++){
        // prefetch epilogue operands for this step (in flight during poll)
        float xp = 0.f, zz = 0.f;
        if (epi){
            xp = xpre[(size_t)(t*BB + b0 + bl)*DD + e0 + el];
            zz = sz[(size_t)(b0 + bl)*TT*DD + (size_t)t*DD + e0 + el];
        }

        if (t > 0){
            if (tid < 32){
                const uint32_t* fp = &g_flagv[g][tid][0];
                const uint32_t target = (uint32_t)t;
                long long guard = 0;
                while (true){
                    uint32_t v = ld_acquire_u32(fp);
                    if (__all_sync(0xffffffffu, v >= target)) break;
                    ++guard;
                    if (guard > 64) __nanosleep(40);
                    if (guard > 8000000LL) break;   // anti-hang bailout
                }
            }
            __syncthreads();
        }

        const float* hb = g_h[t&1] + (size_t)(b0 + bA)*DD + kh*320 + (ll << 2);
        ulonglong2 h0 = ldcg_u2(hb);
        ulonglong2 h1 = ldcg_u2(hb + DD);

        ull acc[2][10];
        #pragma unroll
        for (int b=0;b<2;b++)
            #pragma unroll
            for (int e=0;e<10;e++) acc[b][e]=0ULL;

        #pragma unroll
        for (int it=0; it<5; it++){
            ulonglong2 hn0, hn1;
            if (it < 4){
                const float* hb2 = hb + (it+1)*64;
                hn0 = ldcg_u2(hb2);
                hn1 = ldcg_u2(hb2 + DD);
            }
            const float* wp = wbase + it*64;
            #pragma unroll
            for (int e=0;e<10;e++){
                ulonglong2 wv = *(const ulonglong2*)(wp + (size_t)e*DD);
                acc[0][e] = ffma2(h0.x, wv.x, acc[0][e]);
                acc[0][e] = ffma2(h0.y, wv.y, acc[0][e]);
                acc[1][e] = ffma2(h1.x, wv.x, acc[1][e]);
                acc[1][e] = ffma2(h1.y, wv.y, acc[1][e]);
            }
            h0=hn0; h1=hn1;
        }

        // 4-stage shfl reduction within 16-lane half-warps (k-quads)
        float s[2][10];
        #pragma unroll
        for (int b=0;b<2;b++)
            #pragma unroll
            for (int e=0;e<10;e++) s[b][e] = hadd(acc[b][e]);
        #pragma unroll
        for (int d=1; d<16; d<<=1){
            #pragma unroll
            for (int b=0;b<2;b++)
                #pragma unroll
                for (int e=0;e<10;e++)
                    s[b][e] += __shfl_xor_sync(0xffffffffu, s[b][e], d);
        }
        if (ll == 0){
            float* rp = red + kh*160 + bA*40 + eg*10;   // red[kh][b][e]
            #pragma unroll
            for (int e=0;e<10;e+=2){
                *(float2*)(rp + e)      = make_float2(s[0][e], s[0][e+1]);
                *(float2*)(rp + 40 + e) = make_float2(s[1][e], s[1][e+1]);
            }
        }
        __syncthreads();

        float hval = 0.f;
        if (epi){
            const float* rp = red + bl*40 + el;
            float ssum = rp[0] + rp[160] + rp[320] + rp[480];
            hval = tanh_fast(xp + ssum);
            __stcg(&g_h[(t+1)&1][(size_t)(b0 + bl)*DD + e0 + el], hval);
        }
        __syncthreads();                       // all h stores of this CTA done

        if (tid == 0) st_release_u32(&g_flagv[g][c][0], (uint32_t)(t+1));

        // off-critical-path writes (consumers only need g_h + flag)
        if (epi){
            float op = hval * zz;
            size_t oidx = (size_t)(t*BB + b0 + bl)*DD + e0 + el;
            bf16 hi, lo; hilo(op, hi, lo);
            ot_hi[oidx] = hi;
            ot_lo[oidx] = lo;
            if (dout_h != nullptr && t == TT-1) dout_h[(size_t)(b0 + bl)*DD + e0 + el] = hval;
        }
    }
}

// ============================================================================
extern "C" void kernel_launch(void* const* d_in, const int* in_sizes, int n_in,
                              void* d_out, int out_size){
    const float* x     = (const float*)d_in[0];
    const float* W_in  = (const float*)d_in[1];
    const float* W_out = (const float*)d_in[2];
    const float* W_x   = (const float*)d_in[3];
    const float* W_h   = (const float*)d_in[4];
    const float* bias  = (const float*)d_in[5];
    float* out = (float*)d_out;

    const int recur_smem = (EPC*DD + 4*4*40 + 32) * 4;     // ~207.5 KB
    cudaFuncSetAttribute(recur_kernel, cudaFuncAttributeMaxDynamicSharedMemorySize, recur_smem);

    float* dout_h = (out_size >= BT*DD + BB*DD) ? (out + (size_t)BT*DD) : nullptr;

    float *sz_p, *xpre_p;
    bf16 *xt_hi, *xt_lo, *pt_hi, *pt_lo, *ot_hi, *ot_lo;
    bf16 *wi_hi, *wi_lo, *wx_hi, *wx_lo, *wo_hi, *wo_lo;
    cudaGetSymbolAddress((void**)&sz_p,   g_sz);
    cudaGetSymbolAddress((void**)&xpre_p, g_xpre);
    cudaGetSymbolAddress((void**)&xt_hi,  g_xt_hi);
    cudaGetSymbolAddress((void**)&xt_lo,  g_xt_lo);
    cudaGetSymbolAddress((void**)&pt_hi,  g_pt_hi);
    cudaGetSymbolAddress((void**)&pt_lo,  g_pt_lo);
    cudaGetSymbolAddress((void**)&ot_hi,  g_ot_hi);
    cudaGetSymbolAddress((void**)&ot_lo,  g_ot_lo);
    cudaGetSymbolAddress((void**)&wi_hi,  g_wi_hi);
    cudaGetSymbolAddress((void**)&wi_lo,  g_wi_lo);
    cudaGetSymbolAddress((void**)&wx_hi,  g_wx_hi);
    cudaGetSymbolAddress((void**)&wx_lo,  g_wx_lo);
    cudaGetSymbolAddress((void**)&wo_hi,  g_wo_hi);
    cudaGetSymbolAddress((void**)&wo_lo,  g_wo_lo);

    reset_kernel<<<80, 256>>>();

    convert_hilo<<<(BT*DD/4 + 255)/256, 256>>>(x,     xt_hi, xt_lo, BT*DD/4);
    convert_hilo<<<(2*DD*DD/4 + 255)/256, 256>>>(W_in,  wi_hi, wi_lo, 2*DD*DD/4);
    convert_hilo<<<(DD*DD/4 + 255)/256, 256>>>(W_x,   wx_hi, wx_lo, DD*DD/4);
    convert_hilo<<<(DD*DD/4 + 255)/256, 256>>>(W_out, wo_hi, wo_lo, DD*DD/4);

    gemm_mma<0><<<dim3(BT/128, (2*DD)/128), 256>>>(xt_hi, xt_lo, wi_hi, wi_lo,
                                                   nullptr, sz_p, pt_hi, pt_lo);

    gemm_mma<1><<<dim3(BT/128, DD/128), 256>>>(pt_hi, pt_lo, wx_hi, wx_lo,
                                               bias, xpre_p, nullptr, nullptr);

    recur_kernel<<<NGRP*GCTAS, RTHREADS, recur_smem>>>(W_h, xpre_p, sz_p, ot_hi, ot_lo, dout_h);

    gemm_mma<2><<<dim3(BT/128, DD/128), 256>>>(ot_hi, ot_lo, wo_hi, wo_lo,
                                               nullptr, out, nullptr, nullptr);
}